// round 1
// baseline (speedup 1.0000x reference)
#include <cuda_runtime.h>
#include <math.h>

#define BN_  12
#define CI_  512
#define FHh  16
#define FWw  44
#define HWp  704
#define DD   112
#define COo  80
#define CH   192
#define NPTS (BN_*DD*HWp)

__device__ float g_h1[BN_*CI_*HWp];
__device__ float g_h2[BN_*CI_*HWp];
__device__ float g_hf[BN_*CH*HWp];
__device__ float g_ctx[BN_*HWp*COo];
__device__ int   g_cells[NPTS];
__device__ float g_geo[BN_*52];

// ---------------- geometry setup (12 threads, double precision) ----------------
__device__ void inv4d(const double* a_in, double* out) {
    double a[4][8];
    for (int r = 0; r < 4; r++) {
        for (int c = 0; c < 4; c++) { a[r][c] = a_in[r*4+c]; a[r][4+c] = (r == c) ? 1.0 : 0.0; }
    }
    for (int col = 0; col < 4; col++) {
        int piv = col; double best = fabs(a[col][col]);
        for (int r = col+1; r < 4; r++) { double t = fabs(a[r][col]); if (t > best) { best = t; piv = r; } }
        if (piv != col) for (int c = 0; c < 8; c++) { double t = a[col][c]; a[col][c] = a[piv][c]; a[piv][c] = t; }
        double dinv = 1.0 / a[col][col];
        for (int c = 0; c < 8; c++) a[col][c] *= dinv;
        for (int r = 0; r < 4; r++) {
            if (r == col) continue;
            double f = a[r][col];
            for (int c = 0; c < 8; c++) a[r][c] -= f * a[col][c];
        }
    }
    for (int r = 0; r < 4; r++) for (int c = 0; c < 4; c++) out[r*4+c] = a[r][4+c];
}

__device__ void mm4(const double* A, const double* B, double* C) {
    for (int r = 0; r < 4; r++) for (int c = 0; c < 4; c++) {
        double s = 0.0;
        for (int k = 0; k < 4; k++) s += A[r*4+k] * B[k*4+c];
        C[r*4+c] = s;
    }
}

__global__ void geo_setup(const float* __restrict__ s2e, const float* __restrict__ s2v,
                          const float* __restrict__ intrin, const float* __restrict__ ida,
                          const float* __restrict__ refh, const float* __restrict__ bda) {
    int i = threadIdx.x;
    if (i >= BN_) return;
    int b = i / 6;
    double M[16], V[16], I[16], E[16], BD[16];
    for (int k = 0; k < 16; k++) {
        M[k] = ida[i*16+k]; V[k] = s2v[i*16+k]; I[k] = intrin[i*16+k];
        E[k] = s2e[i*16+k]; BD[k] = bda[b*16+k];
    }
    double Minv[16], Iinv[16], Vinv[16], CV[16], T[16], CEB[16];
    inv4d(M, Minv); inv4d(I, Iinv); inv4d(V, Vinv);
    mm4(V, Iinv, CV);
    mm4(E, Vinv, T);
    mm4(BD, T, CEB);
    float* G = g_geo + i*52;
    for (int k = 0; k < 16; k++) { G[k] = (float)Minv[k]; G[16+k] = (float)CV[k]; G[32+k] = (float)CEB[k]; }
    G[48] = refh[i];
}

// ---------------- 3x3 conv + BN + ReLU ----------------
// grid: (y=16, co_tile=8, n=12), block: 128 threads
// thread: (col 0..31, xg 0..3) -> computes co {co0+col, co0+col+32} x 11 consecutive x
__global__ void conv3x3(const float* __restrict__ in_ext, int in_sel, int out_sel,
                        const float* __restrict__ wt,
                        const float* __restrict__ gp, const float* __restrict__ bp,
                        const float* __restrict__ mp, const float* __restrict__ vp) {
    const int y   = blockIdx.x;
    const int co0 = blockIdx.y * 64;
    const int n   = blockIdx.z;
    const int tid = threadIdx.x;
    const int col = tid & 31;
    const int xg  = tid >> 5;
    const int xb  = xg * 11;

    const float* in  = (in_sel == 0) ? in_ext : g_h1;
    float* out = (out_sel == 0) ? g_h1 : g_h2;

    __shared__ float sW[8][9][64];
    __shared__ float sIn[8][3][48];

    float acc0[11], acc1[11];
#pragma unroll
    for (int i = 0; i < 11; i++) { acc0[i] = 0.f; acc1[i] = 0.f; }

    const float* inp = in + (size_t)n * CI_ * HWp;

    for (int ci0 = 0; ci0 < CI_; ci0 += 8) {
        __syncthreads();
        for (int e = tid; e < 8*9*64; e += 128) {
            int cc = e & 63;
            int k  = (e >> 6) % 9;
            int ci = e / 576;
            sW[ci][k][cc] = wt[((size_t)(co0+cc)*CI_ + ci0 + ci)*9 + k];
        }
        for (int e = tid; e < 8*3*46; e += 128) {
            int j  = e % 46;
            int r  = (e / 46) % 3;
            int ci = e / 138;
            int yy = y + r - 1;
            int xx = j - 1;
            float val = 0.f;
            if (yy >= 0 && yy < FHh && xx >= 0 && xx < FWw)
                val = inp[((ci0+ci)*FHh + yy)*FWw + xx];
            sIn[ci][r][j] = val;
        }
        __syncthreads();
#pragma unroll 2
        for (int ci = 0; ci < 8; ci++) {
#pragma unroll
            for (int ky = 0; ky < 3; ky++) {
                float vv[13];
#pragma unroll
                for (int j = 0; j < 13; j++) vv[j] = sIn[ci][ky][xb + j];
#pragma unroll
                for (int kx = 0; kx < 3; kx++) {
                    float w0 = sW[ci][ky*3+kx][col];
                    float w1 = sW[ci][ky*3+kx][col+32];
#pragma unroll
                    for (int i = 0; i < 11; i++) {
                        acc0[i] = fmaf(w0, vv[i+kx], acc0[i]);
                        acc1[i] = fmaf(w1, vv[i+kx], acc1[i]);
                    }
                }
            }
        }
    }

    int coA = co0 + col;
    int coB = co0 + col + 32;
    float sA = __fdiv_rn(gp[coA], __fsqrt_rn(vp[coA] + 1e-5f));
    float bA = bp[coA] - mp[coA]*sA;
    float sB = __fdiv_rn(gp[coB], __fsqrt_rn(vp[coB] + 1e-5f));
    float bB = bp[coB] - mp[coB]*sB;
    float* oA = out + (((size_t)n*CI_ + coA)*FHh + y)*FWw + xb;
    float* oB = out + (((size_t)n*CI_ + coB)*FHh + y)*FWw + xb;
#pragma unroll
    for (int i = 0; i < 11; i++) {
        oA[i] = fmaxf(fmaf(acc0[i], sA, bA), 0.f);
        oB[i] = fmaxf(fmaf(acc1[i], sB, bB), 0.f);
    }
}

// ---------------- 1x1 conv (512 -> 192) + bias ----------------
__global__ void conv1x1(const float* __restrict__ wt, const float* __restrict__ bias) {
    int gid = blockIdx.x * 256 + threadIdx.x;
    const int total = BN_ * 48 * HWp;
    if (gid >= total) return;
    int p   = gid % HWp;
    int t   = gid / HWp;
    int cog = t % 48;
    int n   = t / 48;
    int cob = cog * 4;
    float a0 = bias[cob], a1 = bias[cob+1], a2 = bias[cob+2], a3 = bias[cob+3];
    const float* ip = g_h2 + (size_t)n * CI_ * HWp + p;
    const float* w0 = wt + (size_t)cob * CI_;
#pragma unroll 4
    for (int ci = 0; ci < CI_; ci++) {
        float x = ip[(size_t)ci * HWp];
        a0 = fmaf(w0[ci],          x, a0);
        a1 = fmaf(w0[CI_ + ci],    x, a1);
        a2 = fmaf(w0[2*CI_ + ci],  x, a2);
        a3 = fmaf(w0[3*CI_ + ci],  x, a3);
    }
    float* op = g_hf + ((size_t)n * CH + cob) * HWp + p;
    op[0] = a0; op[HWp] = a1; op[2*HWp] = a2; op[3*HWp] = a3;
}

// ---------------- depth softmax over first 112 channels ----------------
__global__ void softmax_d() {
    int gid = blockIdx.x * 128 + threadIdx.x;
    if (gid >= BN_ * HWp) return;
    int p = gid % HWp;
    int n = gid / HWp;
    float* base = g_hf + (size_t)n * CH * HWp + p;
    float mx = -1e30f;
    for (int d = 0; d < DD; d++) mx = fmaxf(mx, base[(size_t)d * HWp]);
    float s = 0.f;
    for (int d = 0; d < DD; d++) s += expf(base[(size_t)d * HWp] - mx);
    for (int d = 0; d < DD; d++) base[(size_t)d * HWp] = __fdiv_rn(expf(base[(size_t)d * HWp] - mx), s);
}

// ---------------- context transpose to [n][p][c] (coalesced scatter reads) ----------------
__global__ void ctx_t() {
    int gid = blockIdx.x * 256 + threadIdx.x;
    if (gid >= BN_ * HWp * COo) return;
    int c = gid % COo;
    int t = gid / COo;
    int p = t % HWp;
    int n = t / HWp;
    g_ctx[gid] = g_hf[((size_t)n * CH + DD + c) * HWp + p];
}

// ---------------- per-point voxel index ----------------
__global__ void cells_k() {
    int gid = blockIdx.x * 256 + threadIdx.x;
    if (gid >= NPTS) return;
    int p = gid % HWp;
    int t = gid / HWp;
    int d = t % DD;
    int n = t / DD;
    int wq = p % FWw;
    int hq = p / FWw;

    float X   = wq * (703.0f / 43.0f);
    float Y   = hq * 17.0f;
    float dep = 2.0f + d * (56.0f / 111.0f);

    const float* G = g_geo + n * 52;
    float p0 = G[0]*X  + G[1]*Y  + G[2]*dep  + G[3];
    float p1 = G[4]*X  + G[5]*Y  + G[6]*dep  + G[7];
    float p2 = G[8]*X  + G[9]*Y  + G[10]*dep + G[11];
    float p3 = G[12]*X + G[13]*Y + G[14]*dep + G[15];

    float height = G[48] - p2;
    float c0 = 10.f * p0, c1 = 10.f * p1, c2 = 10.f, c3 = p3;

    const float* CVm = G + 16;
    float q0 = CVm[0]*c0  + CVm[1]*c1  + CVm[2]*c2  + CVm[3]*c3;
    float q1 = CVm[4]*c0  + CVm[5]*c1  + CVm[6]*c2  + CVm[7]*c3;
    float q2 = CVm[8]*c0  + CVm[9]*c1  + CVm[10]*c2 + CVm[11]*c3;

    float ratio = __fdiv_rn(height, q1);
    float r0 = q0 * ratio, r1 = q1 * ratio, r2 = q2 * ratio;

    const float* E = G + 32;
    float g0 = E[0]*r0 + E[1]*r1 + E[2]*r2  + E[3];
    float g1 = E[4]*r0 + E[5]*r1 + E[6]*r2  + E[7];
    float g2 = E[8]*r0 + E[9]*r1 + E[10]*r2 + E[11];

    const float lo = -50.8f - 0.4f;          // matches f32(vcoord) - f32(vsize/2)
    float fx = __fdiv_rn(g0 - lo, 0.8f);
    float fy = __fdiv_rn(g1 - lo, 0.8f);
    float fz = __fdiv_rn(g2 + 5.0f, 8.0f);   // lo_z = -5 exact
    int ix = (int)fx;                         // trunc-toward-zero, matches XLA f32->s32
    int iy = (int)fy;
    int iz = (int)fz;
    bool valid = (ix >= 0) && (iy >= 0) && (iz >= 0) && (ix < 128) && (iy < 128) && (iz < 1);
    g_cells[gid] = valid ? (iy * 128 + ix) : -1;
}

// ---------------- zero output ----------------
__global__ void zero_k(float* __restrict__ out, int nElem) {
    int gid = blockIdx.x * 256 + threadIdx.x;
    if (gid < nElem) out[gid] = 0.f;
}

// ---------------- scatter-add splat ----------------
__global__ void scatter_k(float* __restrict__ out) {
    int t = blockIdx.x * 256 + threadIdx.x;
    const int total = NPTS * COo;   // 75,694,080
    if (t >= total) return;
    int c  = t % COo;
    int pi = t / COo;
    int cell = g_cells[pi];
    if (cell < 0) return;
    int p  = pi % HWp;
    int t2 = pi / HWp;
    int d  = t2 % DD;
    int n  = t2 / DD;
    int b  = (n >= 6) ? 1 : 0;
    float depv = g_hf[((size_t)n * CH + d) * HWp + p];
    float ctxv = g_ctx[((size_t)n * HWp + p) * COo + c];
    atomicAdd(out + ((size_t)(b * COo + c)) * 16384 + cell, depv * ctxv);
}

// ---------------- launch ----------------
extern "C" void kernel_launch(void* const* d_in, const int* in_sizes, int n_in,
                              void* d_out, int out_size) {
    const float* feat   = (const float*)d_in[0];
    const float* w1     = (const float*)d_in[1];
    const float* g1     = (const float*)d_in[2];
    const float* b1     = (const float*)d_in[3];
    const float* m1     = (const float*)d_in[4];
    const float* v1     = (const float*)d_in[5];
    const float* w2     = (const float*)d_in[6];
    const float* g2     = (const float*)d_in[7];
    const float* b2     = (const float*)d_in[8];
    const float* m2     = (const float*)d_in[9];
    const float* v2     = (const float*)d_in[10];
    const float* w_out  = (const float*)d_in[11];
    const float* b_out  = (const float*)d_in[12];
    const float* s2e    = (const float*)d_in[13];
    const float* s2v    = (const float*)d_in[14];
    const float* intrin = (const float*)d_in[15];
    const float* ida    = (const float*)d_in[16];
    const float* refh   = (const float*)d_in[17];
    const float* bda    = (const float*)d_in[18];

    geo_setup<<<1, 32>>>(s2e, s2v, intrin, ida, refh, bda);

    dim3 cgrid(FHh, 8, BN_);
    conv3x3<<<cgrid, 128>>>(feat,    0, 0, w1, g1, b1, m1, v1);
    conv3x3<<<cgrid, 128>>>(nullptr, 1, 1, w2, g2, b2, m2, v2);

    conv1x1<<<(BN_*48*HWp + 255) / 256, 256>>>(w_out, b_out);
    softmax_d<<<(BN_*HWp + 127) / 128, 128>>>();
    ctx_t<<<(BN_*HWp*COo + 255) / 256, 256>>>();
    cells_k<<<(NPTS + 255) / 256, 256>>>();

    zero_k<<<(out_size + 255) / 256, 256>>>((float*)d_out, out_size);
    scatter_k<<<(NPTS*COo + 255) / 256, 256>>>((float*)d_out);
}

// round 2
// speedup vs baseline: 1.0002x; 1.0002x over previous
#include <cuda_runtime.h>
#include <math.h>

#define BN_  12
#define CI_  512
#define FHh  16
#define FWw  44
#define HWp  704
#define DD   112
#define COo  80
#define CH   192
#define NPTS (BN_*DD*HWp)

__device__ float g_h1[BN_*CI_*HWp];
__device__ float g_h2[BN_*CI_*HWp];
__device__ float g_hf[BN_*CH*HWp];
__device__ float g_ctx[BN_*HWp*COo];
__device__ int   g_cells[NPTS];
__device__ float g_geo[BN_*52];

// ---------------- geometry setup (12 threads, double precision) ----------------
__device__ void inv4d(const double* a_in, double* out) {
    double a[4][8];
    for (int r = 0; r < 4; r++) {
        for (int c = 0; c < 4; c++) { a[r][c] = a_in[r*4+c]; a[r][4+c] = (r == c) ? 1.0 : 0.0; }
    }
    for (int col = 0; col < 4; col++) {
        int piv = col; double best = fabs(a[col][col]);
        for (int r = col+1; r < 4; r++) { double t = fabs(a[r][col]); if (t > best) { best = t; piv = r; } }
        if (piv != col) for (int c = 0; c < 8; c++) { double t = a[col][c]; a[col][c] = a[piv][c]; a[piv][c] = t; }
        double dinv = 1.0 / a[col][col];
        for (int c = 0; c < 8; c++) a[col][c] *= dinv;
        for (int r = 0; r < 4; r++) {
            if (r == col) continue;
            double f = a[r][col];
            for (int c = 0; c < 8; c++) a[r][c] -= f * a[col][c];
        }
    }
    for (int r = 0; r < 4; r++) for (int c = 0; c < 4; c++) out[r*4+c] = a[r][4+c];
}

__device__ void mm4(const double* A, const double* B, double* C) {
    for (int r = 0; r < 4; r++) for (int c = 0; c < 4; c++) {
        double s = 0.0;
        for (int k = 0; k < 4; k++) s += A[r*4+k] * B[k*4+c];
        C[r*4+c] = s;
    }
}

__global__ void geo_setup(const float* __restrict__ s2e, const float* __restrict__ s2v,
                          const float* __restrict__ intrin, const float* __restrict__ ida,
                          const float* __restrict__ refh, const float* __restrict__ bda) {
    int i = threadIdx.x;
    if (i >= BN_) return;
    int b = i / 6;
    double M[16], V[16], I[16], E[16], BD[16];
    for (int k = 0; k < 16; k++) {
        M[k] = ida[i*16+k]; V[k] = s2v[i*16+k]; I[k] = intrin[i*16+k];
        E[k] = s2e[i*16+k]; BD[k] = bda[b*16+k];
    }
    double Minv[16], Iinv[16], Vinv[16], CV[16], T[16], CEB[16];
    inv4d(M, Minv); inv4d(I, Iinv); inv4d(V, Vinv);
    mm4(V, Iinv, CV);
    mm4(E, Vinv, T);
    mm4(BD, T, CEB);
    float* G = g_geo + i*52;
    for (int k = 0; k < 16; k++) { G[k] = (float)Minv[k]; G[16+k] = (float)CV[k]; G[32+k] = (float)CEB[k]; }
    G[48] = refh[i];
}

// ---------------- 3x3 conv + BN + ReLU ----------------
// grid: (y=16, co_tile=8, n=12), block: 128 threads
// thread: (col 0..31, xg 0..3) -> computes co {co0+col, co0+col+32} x 11 consecutive x
__global__ void conv3x3(const float* __restrict__ in_ext, int in_sel, int out_sel,
                        const float* __restrict__ wt,
                        const float* __restrict__ gp, const float* __restrict__ bp,
                        const float* __restrict__ mp, const float* __restrict__ vp) {
    const int y   = blockIdx.x;
    const int co0 = blockIdx.y * 64;
    const int n   = blockIdx.z;
    const int tid = threadIdx.x;
    const int col = tid & 31;
    const int xg  = tid >> 5;
    const int xb  = xg * 11;

    const float* in  = (in_sel == 0) ? in_ext : g_h1;
    float* out = (out_sel == 0) ? g_h1 : g_h2;

    __shared__ float sW[8][9][64];
    __shared__ float sIn[8][3][48];

    float acc0[11], acc1[11];
#pragma unroll
    for (int i = 0; i < 11; i++) { acc0[i] = 0.f; acc1[i] = 0.f; }

    const float* inp = in + (size_t)n * CI_ * HWp;

    for (int ci0 = 0; ci0 < CI_; ci0 += 8) {
        __syncthreads();
        for (int e = tid; e < 8*9*64; e += 128) {
            int cc = e & 63;
            int k  = (e >> 6) % 9;
            int ci = e / 576;
            sW[ci][k][cc] = wt[((size_t)(co0+cc)*CI_ + ci0 + ci)*9 + k];
        }
        for (int e = tid; e < 8*3*46; e += 128) {
            int j  = e % 46;
            int r  = (e / 46) % 3;
            int ci = e / 138;
            int yy = y + r - 1;
            int xx = j - 1;
            float val = 0.f;
            if (yy >= 0 && yy < FHh && xx >= 0 && xx < FWw)
                val = inp[((ci0+ci)*FHh + yy)*FWw + xx];
            sIn[ci][r][j] = val;
        }
        __syncthreads();
#pragma unroll 2
        for (int ci = 0; ci < 8; ci++) {
#pragma unroll
            for (int ky = 0; ky < 3; ky++) {
                float vv[13];
#pragma unroll
                for (int j = 0; j < 13; j++) vv[j] = sIn[ci][ky][xb + j];
#pragma unroll
                for (int kx = 0; kx < 3; kx++) {
                    float w0 = sW[ci][ky*3+kx][col];
                    float w1 = sW[ci][ky*3+kx][col+32];
#pragma unroll
                    for (int i = 0; i < 11; i++) {
                        acc0[i] = fmaf(w0, vv[i+kx], acc0[i]);
                        acc1[i] = fmaf(w1, vv[i+kx], acc1[i]);
                    }
                }
            }
        }
    }

    int coA = co0 + col;
    int coB = co0 + col + 32;
    float sA = __fdiv_rn(gp[coA], __fsqrt_rn(vp[coA] + 1e-5f));
    float bA = bp[coA] - mp[coA]*sA;
    float sB = __fdiv_rn(gp[coB], __fsqrt_rn(vp[coB] + 1e-5f));
    float bB = bp[coB] - mp[coB]*sB;
    float* oA = out + (((size_t)n*CI_ + coA)*FHh + y)*FWw + xb;
    float* oB = out + (((size_t)n*CI_ + coB)*FHh + y)*FWw + xb;
#pragma unroll
    for (int i = 0; i < 11; i++) {
        oA[i] = fmaxf(fmaf(acc0[i], sA, bA), 0.f);
        oB[i] = fmaxf(fmaf(acc1[i], sB, bB), 0.f);
    }
}

// ---------------- 1x1 conv (512 -> 192) + bias ----------------
__global__ void conv1x1(const float* __restrict__ wt, const float* __restrict__ bias) {
    int gid = blockIdx.x * 256 + threadIdx.x;
    const int total = BN_ * 48 * HWp;
    if (gid >= total) return;
    int p   = gid % HWp;
    int t   = gid / HWp;
    int cog = t % 48;
    int n   = t / 48;
    int cob = cog * 4;
    float a0 = bias[cob], a1 = bias[cob+1], a2 = bias[cob+2], a3 = bias[cob+3];
    const float* ip = g_h2 + (size_t)n * CI_ * HWp + p;
    const float* w0 = wt + (size_t)cob * CI_;
#pragma unroll 4
    for (int ci = 0; ci < CI_; ci++) {
        float x = ip[(size_t)ci * HWp];
        a0 = fmaf(w0[ci],          x, a0);
        a1 = fmaf(w0[CI_ + ci],    x, a1);
        a2 = fmaf(w0[2*CI_ + ci],  x, a2);
        a3 = fmaf(w0[3*CI_ + ci],  x, a3);
    }
    float* op = g_hf + ((size_t)n * CH + cob) * HWp + p;
    op[0] = a0; op[HWp] = a1; op[2*HWp] = a2; op[3*HWp] = a3;
}

// ---------------- depth softmax over first 112 channels ----------------
__global__ void softmax_d() {
    int gid = blockIdx.x * 128 + threadIdx.x;
    if (gid >= BN_ * HWp) return;
    int p = gid % HWp;
    int n = gid / HWp;
    float* base = g_hf + (size_t)n * CH * HWp + p;
    float mx = -1e30f;
    for (int d = 0; d < DD; d++) mx = fmaxf(mx, base[(size_t)d * HWp]);
    float s = 0.f;
    for (int d = 0; d < DD; d++) s += expf(base[(size_t)d * HWp] - mx);
    for (int d = 0; d < DD; d++) base[(size_t)d * HWp] = __fdiv_rn(expf(base[(size_t)d * HWp] - mx), s);
}

// ---------------- context transpose to [n][p][c] (coalesced scatter reads) ----------------
__global__ void ctx_t() {
    int gid = blockIdx.x * 256 + threadIdx.x;
    if (gid >= BN_ * HWp * COo) return;
    int c = gid % COo;
    int t = gid / COo;
    int p = t % HWp;
    int n = t / HWp;
    g_ctx[gid] = g_hf[((size_t)n * CH + DD + c) * HWp + p];
}

// ---------------- per-point voxel index ----------------
__global__ void cells_k() {
    int gid = blockIdx.x * 256 + threadIdx.x;
    if (gid >= NPTS) return;
    int p = gid % HWp;
    int t = gid / HWp;
    int d = t % DD;
    int n = t / DD;
    int wq = p % FWw;
    int hq = p / FWw;

    float X   = wq * (703.0f / 43.0f);
    float Y   = hq * 17.0f;
    float dep = 2.0f + d * (56.0f / 111.0f);

    const float* G = g_geo + n * 52;
    float p0 = G[0]*X  + G[1]*Y  + G[2]*dep  + G[3];
    float p1 = G[4]*X  + G[5]*Y  + G[6]*dep  + G[7];
    float p2 = G[8]*X  + G[9]*Y  + G[10]*dep + G[11];
    float p3 = G[12]*X + G[13]*Y + G[14]*dep + G[15];

    float height = G[48] - p2;
    float c0 = 10.f * p0, c1 = 10.f * p1, c2 = 10.f, c3 = p3;

    const float* CVm = G + 16;
    float q0 = CVm[0]*c0  + CVm[1]*c1  + CVm[2]*c2  + CVm[3]*c3;
    float q1 = CVm[4]*c0  + CVm[5]*c1  + CVm[6]*c2  + CVm[7]*c3;
    float q2 = CVm[8]*c0  + CVm[9]*c1  + CVm[10]*c2 + CVm[11]*c3;

    float ratio = __fdiv_rn(height, q1);
    float r0 = q0 * ratio, r1 = q1 * ratio, r2 = q2 * ratio;

    const float* E = G + 32;
    float g0 = E[0]*r0 + E[1]*r1 + E[2]*r2  + E[3];
    float g1 = E[4]*r0 + E[5]*r1 + E[6]*r2  + E[7];
    float g2 = E[8]*r0 + E[9]*r1 + E[10]*r2 + E[11];

    const float lo = -50.8f - 0.4f;          // matches f32(vcoord) - f32(vsize/2)
    float fx = __fdiv_rn(g0 - lo, 0.8f);
    float fy = __fdiv_rn(g1 - lo, 0.8f);
    float fz = __fdiv_rn(g2 + 5.0f, 8.0f);   // lo_z = -5 exact
    int ix = (int)fx;                         // trunc-toward-zero, matches XLA f32->s32
    int iy = (int)fy;
    int iz = (int)fz;
    bool valid = (ix >= 0) && (iy >= 0) && (iz >= 0) && (ix < 128) && (iy < 128) && (iz < 1);
    g_cells[gid] = valid ? (iy * 128 + ix) : -1;
}

// ---------------- zero output ----------------
__global__ void zero_k(float* __restrict__ out, int nElem) {
    int gid = blockIdx.x * 256 + threadIdx.x;
    if (gid < nElem) out[gid] = 0.f;
}

// ---------------- scatter-add splat ----------------
__global__ void scatter_k(float* __restrict__ out) {
    int t = blockIdx.x * 256 + threadIdx.x;
    const int total = NPTS * COo;   // 75,694,080
    if (t >= total) return;
    int c  = t % COo;
    int pi = t / COo;
    int cell = g_cells[pi];
    if (cell < 0) return;
    int p  = pi % HWp;
    int t2 = pi / HWp;
    int d  = t2 % DD;
    int n  = t2 / DD;
    int b  = (n >= 6) ? 1 : 0;
    float depv = g_hf[((size_t)n * CH + d) * HWp + p];
    float ctxv = g_ctx[((size_t)n * HWp + p) * COo + c];
    atomicAdd(out + ((size_t)(b * COo + c)) * 16384 + cell, depv * ctxv);
}

// ---------------- launch ----------------
extern "C" void kernel_launch(void* const* d_in, const int* in_sizes, int n_in,
                              void* d_out, int out_size) {
    const float* feat   = (const float*)d_in[0];
    const float* w1     = (const float*)d_in[1];
    const float* g1     = (const float*)d_in[2];
    const float* b1     = (const float*)d_in[3];
    const float* m1     = (const float*)d_in[4];
    const float* v1     = (const float*)d_in[5];
    const float* w2     = (const float*)d_in[6];
    const float* g2     = (const float*)d_in[7];
    const float* b2     = (const float*)d_in[8];
    const float* m2     = (const float*)d_in[9];
    const float* v2     = (const float*)d_in[10];
    const float* w_out  = (const float*)d_in[11];
    const float* b_out  = (const float*)d_in[12];
    const float* s2e    = (const float*)d_in[13];
    const float* s2v    = (const float*)d_in[14];
    const float* intrin = (const float*)d_in[15];
    const float* ida    = (const float*)d_in[16];
    const float* refh   = (const float*)d_in[17];
    const float* bda    = (const float*)d_in[18];

    geo_setup<<<1, 32>>>(s2e, s2v, intrin, ida, refh, bda);

    dim3 cgrid(FHh, 8, BN_);
    conv3x3<<<cgrid, 128>>>(feat,    0, 0, w1, g1, b1, m1, v1);
    conv3x3<<<cgrid, 128>>>(nullptr, 1, 1, w2, g2, b2, m2, v2);

    conv1x1<<<(BN_*48*HWp + 255) / 256, 256>>>(w_out, b_out);
    softmax_d<<<(BN_*HWp + 127) / 128, 128>>>();
    ctx_t<<<(BN_*HWp*COo + 255) / 256, 256>>>();
    cells_k<<<(NPTS + 255) / 256, 256>>>();

    zero_k<<<(out_size + 255) / 256, 256>>>((float*)d_out, out_size);
    scatter_k<<<(NPTS*COo + 255) / 256, 256>>>((float*)d_out);
}

// round 4
// speedup vs baseline: 4.0722x; 4.0714x over previous
#include <cuda_runtime.h>
#include <cuda_bf16.h>
#include <math.h>
#include <stdint.h>

#define BN_  12
#define FHh  16
#define FWw  44
#define HWp  704
#define DD   112
#define COo  80
#define CH   192
#define NPTS (BN_*DD*HWp)

#define XROWS 992          // 48 guard + 828 logical + 116 tail guard
#define XOFF  48
#define PADP  828          // 18*46

// ---------------- persistent device buffers ----------------
__device__ __align__(16) __nv_bfloat16 g_x1h[BN_*XROWS*512];
__device__ __align__(16) __nv_bfloat16 g_x1l[BN_*XROWS*512];
__device__ __align__(16) __nv_bfloat16 g_x2h[BN_*XROWS*512];
__device__ __align__(16) __nv_bfloat16 g_x2l[BN_*XROWS*512];
__device__ __align__(16) __nv_bfloat16 g_x3h[BN_*XROWS*512];
__device__ __align__(16) __nv_bfloat16 g_x3l[BN_*XROWS*512];
__device__ __align__(16) __nv_bfloat16 g_w1h[512*9*512];
__device__ __align__(16) __nv_bfloat16 g_w1l[512*9*512];
__device__ __align__(16) __nv_bfloat16 g_w2h[512*9*512];
__device__ __align__(16) __nv_bfloat16 g_w2l[512*9*512];
__device__ __align__(16) __nv_bfloat16 g_woh[256*512];
__device__ __align__(16) __nv_bfloat16 g_wol[256*512];
__device__ __align__(16) float g_hf2[BN_*HWp*CH];
__device__ int   g_cells[NPTS];
__device__ float g_geo[BN_*52];

// ---------------- PTX helpers (family-stable only) ----------------
__device__ __forceinline__ uint32_t smem_u32(const void* p) {
    uint32_t a;
    asm("{ .reg .u64 t; cvta.to.shared.u64 t, %1; cvt.u32.u64 %0, t; }" : "=r"(a) : "l"(p));
    return a;
}
#define CP16(dst, src) \
    asm volatile("cp.async.cg.shared.global [%0], [%1], 16;" :: "r"((uint32_t)(dst)), "l"(src) : "memory")
#define CPCOMMIT() asm volatile("cp.async.commit_group;" ::: "memory")
#define CPWAIT1()  asm volatile("cp.async.wait_group 1;" ::: "memory")
#define CPWAIT0()  asm volatile("cp.async.wait_group 0;" ::: "memory")

__device__ __forceinline__ void ldmx4(uint32_t addr, uint32_t& r0, uint32_t& r1, uint32_t& r2, uint32_t& r3) {
    asm volatile("ldmatrix.sync.aligned.m8n8.x4.shared.b16 {%0,%1,%2,%3}, [%4];"
                 : "=r"(r0), "=r"(r1), "=r"(r2), "=r"(r3) : "r"(addr));
}
__device__ __forceinline__ void mma16816(float* c, const uint32_t* a, uint32_t b0, uint32_t b1) {
    asm volatile("mma.sync.aligned.m16n8k16.row.col.f32.bf16.bf16.f32 "
                 "{%0,%1,%2,%3}, {%4,%5,%6,%7}, {%8,%9}, {%0,%1,%2,%3};"
                 : "+f"(c[0]), "+f"(c[1]), "+f"(c[2]), "+f"(c[3])
                 : "r"(a[0]), "r"(a[1]), "r"(a[2]), "r"(a[3]), "r"(b0), "r"(b1));
}

// ---------------- geometry setup ----------------
__device__ void inv4d(const double* a_in, double* out) {
    double a[4][8];
    for (int r = 0; r < 4; r++)
        for (int c = 0; c < 4; c++) { a[r][c] = a_in[r*4+c]; a[r][4+c] = (r == c) ? 1.0 : 0.0; }
    for (int col = 0; col < 4; col++) {
        int piv = col; double best = fabs(a[col][col]);
        for (int r = col+1; r < 4; r++) { double t = fabs(a[r][col]); if (t > best) { best = t; piv = r; } }
        if (piv != col) for (int c = 0; c < 8; c++) { double t = a[col][c]; a[col][c] = a[piv][c]; a[piv][c] = t; }
        double dinv = 1.0 / a[col][col];
        for (int c = 0; c < 8; c++) a[col][c] *= dinv;
        for (int r = 0; r < 4; r++) {
            if (r == col) continue;
            double f = a[r][col];
            for (int c = 0; c < 8; c++) a[r][c] -= f * a[col][c];
        }
    }
    for (int r = 0; r < 4; r++) for (int c = 0; c < 4; c++) out[r*4+c] = a[r][4+c];
}
__device__ void mm4(const double* A, const double* B, double* C) {
    for (int r = 0; r < 4; r++) for (int c = 0; c < 4; c++) {
        double s = 0.0;
        for (int k = 0; k < 4; k++) s += A[r*4+k] * B[k*4+c];
        C[r*4+c] = s;
    }
}
__global__ void geo_setup(const float* __restrict__ s2e, const float* __restrict__ s2v,
                          const float* __restrict__ intrin, const float* __restrict__ ida,
                          const float* __restrict__ refh, const float* __restrict__ bda) {
    int i = threadIdx.x;
    if (i >= BN_) return;
    int b = i / 6;
    double M[16], V[16], I[16], E[16], BD[16];
    for (int k = 0; k < 16; k++) {
        M[k] = ida[i*16+k]; V[k] = s2v[i*16+k]; I[k] = intrin[i*16+k];
        E[k] = s2e[i*16+k]; BD[k] = bda[b*16+k];
    }
    double Minv[16], Iinv[16], Vinv[16], CV[16], T[16], CEB[16];
    inv4d(M, Minv); inv4d(I, Iinv); inv4d(V, Vinv);
    mm4(V, Iinv, CV); mm4(E, Vinv, T); mm4(BD, T, CEB);
    float* G = g_geo + i*52;
    for (int k = 0; k < 16; k++) { G[k] = (float)Minv[k]; G[16+k] = (float)CV[k]; G[32+k] = (float)CEB[k]; }
    G[48] = refh[i];
}

// ---------------- zero + packing ----------------
__global__ void zero_all() {
    int gid = blockIdx.x * 256 + threadIdx.x;
    const int tot = (BN_*XROWS*512*2) / 16;
    if (gid >= tot) return;
    uint4 z = {0,0,0,0};
    ((uint4*)g_x1h)[gid] = z; ((uint4*)g_x1l)[gid] = z;
    ((uint4*)g_x2h)[gid] = z; ((uint4*)g_x2l)[gid] = z;
    ((uint4*)g_x3h)[gid] = z; ((uint4*)g_x3l)[gid] = z;
}

// tiled transpose pack: feat [n][ci][704] -> g_x1 [n][prow][512] (hi/lo)
__global__ void pack_feat(const float* __restrict__ feat) {
    __shared__ float sm[32][33];
    int n   = blockIdx.z;
    int ci0 = blockIdx.y * 32;
    int p0  = blockIdx.x * 32;
    int tx = threadIdx.x, ty = threadIdx.y;
#pragma unroll
    for (int i = ty; i < 32; i += 8)
        sm[i][tx] = feat[((size_t)(n*512 + ci0 + i)) * HWp + p0 + tx];
    __syncthreads();
    size_t xbase = (size_t)n * XROWS * 512;
#pragma unroll
    for (int i = ty; i < 32; i += 8) {
        int p = p0 + i;
        int y = p / FWw, x = p % FWw;
        int prow = XOFF + (y + 1) * 46 + (x + 1);
        float v = sm[tx][i];
        __nv_bfloat16 h = __float2bfloat16(v);
        size_t o = xbase + (size_t)prow * 512 + ci0 + tx;
        g_x1h[o] = h;
        g_x1l[o] = __float2bfloat16(v - __bfloat162float(h));
    }
}

__global__ void pack_w(const float* __restrict__ w, int which) {
    int gid = blockIdx.x * 256 + threadIdx.x;
    if (gid >= 512*9*512) return;
    int ci = gid & 511;
    int t  = (gid >> 9) % 9;
    int co = gid / (9*512);
    float v = w[((size_t)co*512 + ci)*9 + t];
    __nv_bfloat16 h = __float2bfloat16(v);
    __nv_bfloat16 l = __float2bfloat16(v - __bfloat162float(h));
    if (which == 0) { g_w1h[gid] = h; g_w1l[gid] = l; }
    else            { g_w2h[gid] = h; g_w2l[gid] = l; }
}

__global__ void pack_wo(const float* __restrict__ w) {
    int gid = blockIdx.x * 256 + threadIdx.x;
    if (gid >= 256*512) return;
    int ci = gid & 511;
    int co = gid >> 9;
    float v = (co < CH) ? w[(size_t)co*512 + ci] : 0.f;
    __nv_bfloat16 h = __float2bfloat16(v);
    g_woh[gid] = h;
    g_wol[gid] = __float2bfloat16(v - __bfloat162float(h));
}

// ---------------- HMMA implicit-GEMM conv ----------------
// block 256 (8 warps: warp_m=wid&3 over 4x32 M rows, warp_n=wid>>2 over 2x64 N cols)
// CTA: M=128 positions x N=128 co, K staged in (tap, 64-ci) chunks, double-buffered.
#define ASTRIDE 144              // 72 bf16 per row (64 data + 8 pad)
#define T_A  (128*ASTRIDE)       // 18432
#define OFF_AH 0
#define OFF_AL T_A
#define OFF_BH (2*T_A)
#define OFF_BL (3*T_A)
#define STAGE  (4*T_A)           // 73728
#define SMEM2  (2*STAGE)         // 147456

__global__ void __launch_bounds__(256, 1) conv_mma(
    int xsel, int wsel, int taps, int mode, int ysel,
    const float* __restrict__ q0, const float* __restrict__ q1,
    const float* __restrict__ q2, const float* __restrict__ q3)
{
    extern __shared__ __align__(128) uint8_t smd[];
    const uint32_t sb = smem_u32(smd);
    const int tid  = threadIdx.x;
    const int wid  = tid >> 5;
    const int lane = tid & 31;
    const int wm   = wid & 3;
    const int wn   = wid >> 2;
    const int m0   = blockIdx.x * 128;
    const int co0  = blockIdx.y * 128;
    const int n    = blockIdx.z;

    const __nv_bfloat16 *Xhi, *Xlo, *Whi, *Wlo;
    if (xsel == 0)      { Xhi = g_x1h; Xlo = g_x1l; }
    else if (xsel == 1) { Xhi = g_x2h; Xlo = g_x2l; }
    else                { Xhi = g_x3h; Xlo = g_x3l; }
    if (wsel == 0)      { Whi = g_w1h; Wlo = g_w1l; }
    else if (wsel == 1) { Whi = g_w2h; Wlo = g_w2l; }
    else                { Whi = g_woh; Wlo = g_wol; }

    const int steps   = taps * 8;
    const int wstride = taps * 512;
    const size_t xbase = (size_t)n * XROWS * 512;

    float acc[2][8][4];
#pragma unroll
    for (int a = 0; a < 2; a++)
#pragma unroll
        for (int b = 0; b < 8; b++)
#pragma unroll
            for (int c = 0; c < 4; c++) acc[a][b][c] = 0.f;

    // per-thread cp.async assignments: 4 rows x 1 16B chunk per array per pass? 1024 chunks/array
    auto issue = [&](int s) {
        int t  = s >> 3, ch = s & 7;
        int drow = (taps == 9) ? ((t / 3 - 1) * 46 + (t % 3 - 1)) : 0;
        uint32_t stb = sb + (uint32_t)(s & 1) * STAGE;
        const __nv_bfloat16* xh = Xhi + xbase + (size_t)(XOFF + m0 + drow) * 512 + ch * 64;
        const __nv_bfloat16* xl = Xlo + xbase + (size_t)(XOFF + m0 + drow) * 512 + ch * 64;
        const __nv_bfloat16* wh = Whi + (size_t)co0 * wstride + t * 512 + ch * 64;
        const __nv_bfloat16* wl = Wlo + (size_t)co0 * wstride + t * 512 + ch * 64;
#pragma unroll
        for (int i = 0; i < 4; i++) {
            int idx = i * 256 + tid;       // 0..1023
            int r = idx >> 3, cq = idx & 7;
            uint32_t so = (uint32_t)(r * ASTRIDE + cq * 16);
            CP16(stb + OFF_AH + so, xh + (size_t)r * 512     + cq * 8);
            CP16(stb + OFF_AL + so, xl + (size_t)r * 512     + cq * 8);
            CP16(stb + OFF_BH + so, wh + (size_t)r * wstride + cq * 8);
            CP16(stb + OFF_BL + so, wl + (size_t)r * wstride + cq * 8);
        }
        CPCOMMIT();
    };

    issue(0);
    for (int s = 0; s < steps; s++) {
        if (s + 1 < steps) { issue(s + 1); CPWAIT1(); } else { CPWAIT0(); }
        __syncthreads();
        uint32_t stb = sb + (uint32_t)(s & 1) * STAGE;

        const uint32_t a_row  = (uint32_t)(wm * 32 + (lane & 15));
        const uint32_t a_koff = (uint32_t)((lane >> 4) * 16);
        const uint32_t b_nrow = (uint32_t)(wn * 64 + ((lane >> 4) << 3) + (lane & 7));
        const uint32_t b_koff = (uint32_t)(((lane >> 3) & 1) * 16);

#pragma unroll
        for (int ks = 0; ks < 4; ks++) {
            uint32_t kb = (uint32_t)(ks * 32);
            uint32_t ahi[2][4], alo[2][4];
#pragma unroll
            for (int mt = 0; mt < 2; mt++) {
                uint32_t ra = (a_row + mt * 16) * ASTRIDE + kb + a_koff;
                ldmx4(stb + OFF_AH + ra, ahi[mt][0], ahi[mt][1], ahi[mt][2], ahi[mt][3]);
                ldmx4(stb + OFF_AL + ra, alo[mt][0], alo[mt][1], alo[mt][2], alo[mt][3]);
            }
#pragma unroll
            for (int nt2 = 0; nt2 < 4; nt2++) {
                uint32_t rb = (b_nrow + nt2 * 16) * ASTRIDE + kb + b_koff;
                uint32_t bh0, bh1, bh2, bh3, bl0, bl1, bl2, bl3;
                ldmx4(stb + OFF_BH + rb, bh0, bh1, bh2, bh3);
                ldmx4(stb + OFF_BL + rb, bl0, bl1, bl2, bl3);
#pragma unroll
                for (int mt = 0; mt < 2; mt++) {
                    mma16816(acc[mt][nt2*2],   ahi[mt], bh0, bh1);
                    mma16816(acc[mt][nt2*2+1], ahi[mt], bh2, bh3);
                    mma16816(acc[mt][nt2*2],   ahi[mt], bl0, bl1);
                    mma16816(acc[mt][nt2*2+1], ahi[mt], bl2, bl3);
                    mma16816(acc[mt][nt2*2],   alo[mt], bh0, bh1);
                    mma16816(acc[mt][nt2*2+1], alo[mt], bh2, bh3);
                }
            }
        }
        __syncthreads();
    }

    // ---------------- epilogue ----------------
    const int gid = lane >> 2, tig = lane & 3;
    float sc[16], bb[16];
#pragma unroll
    for (int nt = 0; nt < 8; nt++) {
#pragma unroll
        for (int e = 0; e < 2; e++) {
            int co = co0 + wn * 64 + nt * 8 + tig * 2 + e;
            if (mode == 0) {
                float s = q0[co] / sqrtf(q3[co] + 1e-5f);
                sc[nt*2+e] = s;
                bb[nt*2+e] = q1[co] - q2[co] * s;
            } else {
                sc[nt*2+e] = 1.f;
                bb[nt*2+e] = (co < CH) ? q0[co] : 0.f;
            }
        }
    }

    __nv_bfloat16 *Yh = (ysel == 1) ? g_x2h : g_x3h;
    __nv_bfloat16 *Yl = (ysel == 1) ? g_x2l : g_x3l;

#pragma unroll
    for (int mt = 0; mt < 2; mt++) {
#pragma unroll
        for (int rr = 0; rr < 2; rr++) {
            int p = m0 + wm * 32 + mt * 16 + gid + rr * 8;
            int py = p / 46, px = p % 46;
            bool inter = (p < PADP) && (py >= 1) && (py <= 16) && (px >= 1) && (px <= 44);
            if (!inter) continue;
            if (mode == 0) {
                size_t ob = xbase + (size_t)(XOFF + p) * 512 + co0 + wn * 64;
#pragma unroll
                for (int nt = 0; nt < 8; nt++) {
#pragma unroll
                    for (int e = 0; e < 2; e++) {
                        float v = fmaxf(fmaf(acc[mt][nt][rr*2+e], sc[nt*2+e], bb[nt*2+e]), 0.f);
                        __nv_bfloat16 h = __float2bfloat16(v);
                        size_t o = ob + nt * 8 + tig * 2 + e;
                        Yh[o] = h;
                        Yl[o] = __float2bfloat16(v - __bfloat162float(h));
                    }
                }
            } else {
                int y = py - 1, x = px - 1;
                size_t ob = ((size_t)n * HWp + y * FWw + x) * CH;
#pragma unroll
                for (int nt = 0; nt < 8; nt++) {
#pragma unroll
                    for (int e = 0; e < 2; e++) {
                        int co = co0 + wn * 64 + nt * 8 + tig * 2 + e;
                        if (co < CH)
                            g_hf2[ob + co] = acc[mt][nt][rr*2+e] + bb[nt*2+e];
                    }
                }
            }
        }
    }
}

// ---------------- depth softmax (warp per pixel, channel-last) ----------------
__global__ void softmax2() {
    int r = blockIdx.x * 8 + (threadIdx.x >> 5);
    int lane = threadIdx.x & 31;
    if (r >= BN_ * HWp) return;
    float* row = g_hf2 + (size_t)r * CH;
    float v0 = row[lane], v1 = row[lane+32], v2 = row[lane+64];
    float v3 = (lane < 16) ? row[lane+96] : -1e30f;
    float mx = fmaxf(fmaxf(v0, v1), fmaxf(v2, v3));
#pragma unroll
    for (int o = 16; o; o >>= 1) mx = fmaxf(mx, __shfl_xor_sync(0xFFFFFFFF, mx, o));
    float e0 = expf(v0 - mx), e1 = expf(v1 - mx), e2 = expf(v2 - mx);
    float e3 = (lane < 16) ? expf(v3 - mx) : 0.f;
    float sm = e0 + e1 + e2 + e3;
#pragma unroll
    for (int o = 16; o; o >>= 1) sm += __shfl_xor_sync(0xFFFFFFFF, sm, o);
    float inv = 1.f / sm;
    row[lane] = e0 * inv; row[lane+32] = e1 * inv; row[lane+64] = e2 * inv;
    if (lane < 16) row[lane+96] = e3 * inv;
}

// ---------------- per-point voxel index ----------------
__global__ void cells_k() {
    int gid = blockIdx.x * 256 + threadIdx.x;
    if (gid >= NPTS) return;
    int p = gid % HWp;
    int t = gid / HWp;
    int d = t % DD;
    int n = t / DD;
    int wq = p % FWw;
    int hq = p / FWw;

    float X   = wq * (703.0f / 43.0f);
    float Y   = hq * 17.0f;
    float dep = 2.0f + d * (56.0f / 111.0f);

    const float* G = g_geo + n * 52;
    float p0 = G[0]*X  + G[1]*Y  + G[2]*dep  + G[3];
    float p1 = G[4]*X  + G[5]*Y  + G[6]*dep  + G[7];
    float p2 = G[8]*X  + G[9]*Y  + G[10]*dep + G[11];
    float p3 = G[12]*X + G[13]*Y + G[14]*dep + G[15];

    float height = G[48] - p2;
    float c0 = 10.f * p0, c1 = 10.f * p1, c2 = 10.f, c3 = p3;

    const float* CVm = G + 16;
    float q0 = CVm[0]*c0  + CVm[1]*c1  + CVm[2]*c2  + CVm[3]*c3;
    float q1 = CVm[4]*c0  + CVm[5]*c1  + CVm[6]*c2  + CVm[7]*c3;
    float q2 = CVm[8]*c0  + CVm[9]*c1  + CVm[10]*c2 + CVm[11]*c3;

    float ratio = __fdiv_rn(height, q1);
    float r0 = q0 * ratio, r1 = q1 * ratio, r2 = q2 * ratio;

    const float* E = G + 32;
    float g0 = E[0]*r0 + E[1]*r1 + E[2]*r2  + E[3];
    float g1 = E[4]*r0 + E[5]*r1 + E[6]*r2  + E[7];
    float g2 = E[8]*r0 + E[9]*r1 + E[10]*r2 + E[11];

    const float lo = -50.8f - 0.4f;
    float fx = __fdiv_rn(g0 - lo, 0.8f);
    float fy = __fdiv_rn(g1 - lo, 0.8f);
    float fz = __fdiv_rn(g2 + 5.0f, 8.0f);
    int ix = (int)fx;
    int iy = (int)fy;
    int iz = (int)fz;
    bool valid = (ix >= 0) && (iy >= 0) && (iz >= 0) && (ix < 128) && (iy < 128) && (iz < 1);
    g_cells[gid] = valid ? (iy * 128 + ix) : -1;
}

__global__ void zero_k(float* __restrict__ out, int nElem) {
    int gid = blockIdx.x * 256 + threadIdx.x;
    if (gid < nElem) out[gid] = 0.f;
}

// ---------------- scatter with depth-run merging ----------------
__global__ void scatter2(float* __restrict__ out) {
    int gid = blockIdx.x * 256 + threadIdx.x;
    const int total = BN_ * HWp * COo;
    if (gid >= total) return;
    int c = gid % COo;
    int t = gid / COo;
    int q = t % HWp;
    int n = t / HWp;
    int b = (n >= 6) ? 1 : 0;
    const float* row = g_hf2 + ((size_t)n * HWp + q) * CH;
    float ctxv = row[DD + c];
    float* obase = out + (size_t)(b * COo + c) * 16384;
    const int* cp = g_cells + n * DD * HWp + q;
    int prev = -1; float acc = 0.f;
#pragma unroll 4
    for (int d = 0; d < DD; d++) {
        int cell = cp[d * HWp];
        float dv = row[d];
        if (cell != prev) {
            if (prev >= 0) atomicAdd(obase + prev, acc * ctxv);
            acc = 0.f; prev = cell;
        }
        acc += dv;
    }
    if (prev >= 0) atomicAdd(obase + prev, acc * ctxv);
}

// ---------------- launch ----------------
extern "C" void kernel_launch(void* const* d_in, const int* in_sizes, int n_in,
                              void* d_out, int out_size) {
    const float* feat   = (const float*)d_in[0];
    const float* w1     = (const float*)d_in[1];
    const float* g1     = (const float*)d_in[2];
    const float* b1     = (const float*)d_in[3];
    const float* m1     = (const float*)d_in[4];
    const float* v1     = (const float*)d_in[5];
    const float* w2     = (const float*)d_in[6];
    const float* g2     = (const float*)d_in[7];
    const float* b2     = (const float*)d_in[8];
    const float* m2     = (const float*)d_in[9];
    const float* v2     = (const float*)d_in[10];
    const float* w_out  = (const float*)d_in[11];
    const float* b_out  = (const float*)d_in[12];
    const float* s2e    = (const float*)d_in[13];
    const float* s2v    = (const float*)d_in[14];
    const float* intrin = (const float*)d_in[15];
    const float* ida    = (const float*)d_in[16];
    const float* refh   = (const float*)d_in[17];
    const float* bda    = (const float*)d_in[18];

    cudaFuncSetAttribute(conv_mma, cudaFuncAttributeMaxDynamicSharedMemorySize, SMEM2);

    geo_setup<<<1, 32>>>(s2e, s2v, intrin, ida, refh, bda);
    zero_all<<<((BN_*XROWS*512*2/16) + 255) / 256, 256>>>();
    pack_feat<<<dim3(HWp/32, 16, BN_), dim3(32, 8)>>>(feat);
    pack_w<<<(512*9*512 + 255) / 256, 256>>>(w1, 0);
    pack_w<<<(512*9*512 + 255) / 256, 256>>>(w2, 1);
    pack_wo<<<(256*512 + 255) / 256, 256>>>(w_out);

    conv_mma<<<dim3(7, 4, BN_), 256, SMEM2>>>(0, 0, 9, 0, 1, g1, b1, m1, v1);
    conv_mma<<<dim3(7, 4, BN_), 256, SMEM2>>>(1, 1, 9, 0, 2, g2, b2, m2, v2);
    conv_mma<<<dim3(7, 2, BN_), 256, SMEM2>>>(2, 2, 1, 1, 0, b_out, b_out, b_out, b_out);

    softmax2<<<(BN_*HWp + 7) / 8, 256>>>();
    cells_k<<<(NPTS + 255) / 256, 256>>>();
    zero_k<<<(out_size + 255) / 256, 256>>>((float*)d_out, out_size);
    scatter2<<<(BN_*HWp*COo + 255) / 256, 256>>>((float*)d_out);
}

// round 5
// speedup vs baseline: 4.1889x; 1.0287x over previous
#include <cuda_runtime.h>
#include <cuda_bf16.h>
#include <math.h>
#include <stdint.h>

#define BN_  12
#define FHh  16
#define FWw  44
#define HWp  704
#define DD   112
#define COo  80
#define CH   192
#define NPTS (BN_*DD*HWp)
#define RAYS (BN_*HWp)

#define XROWS 992          // 48 guard + 828 logical + 116 tail guard
#define XOFF  48
#define PADP  828          // 18*46

// ---------------- persistent device buffers ----------------
__device__ __align__(16) __nv_bfloat16 g_x1h[BN_*XROWS*512];
__device__ __align__(16) __nv_bfloat16 g_x1l[BN_*XROWS*512];
__device__ __align__(16) __nv_bfloat16 g_x2h[BN_*XROWS*512];
__device__ __align__(16) __nv_bfloat16 g_x2l[BN_*XROWS*512];
__device__ __align__(16) __nv_bfloat16 g_x3h[BN_*XROWS*512];
__device__ __align__(16) __nv_bfloat16 g_x3l[BN_*XROWS*512];
__device__ __align__(16) __nv_bfloat16 g_w1h[512*9*512];
__device__ __align__(16) __nv_bfloat16 g_w1l[512*9*512];
__device__ __align__(16) __nv_bfloat16 g_w2h[512*9*512];
__device__ __align__(16) __nv_bfloat16 g_w2l[512*9*512];
__device__ __align__(16) __nv_bfloat16 g_woh[256*512];
__device__ __align__(16) __nv_bfloat16 g_wol[256*512];
__device__ __align__(16) float g_hf2[BN_*HWp*CH];
__device__ __align__(16) float g_bev[2*16384*COo];   // scratch BEV, channel-contiguous
__device__ int   g_cells[NPTS];                       // [ray][d]
__device__ float g_geo[BN_*52];

// ---------------- PTX helpers (family-stable only) ----------------
__device__ __forceinline__ uint32_t smem_u32(const void* p) {
    uint32_t a;
    asm("{ .reg .u64 t; cvta.to.shared.u64 t, %1; cvt.u32.u64 %0, t; }" : "=r"(a) : "l"(p));
    return a;
}
#define CP16(dst, src) \
    asm volatile("cp.async.cg.shared.global [%0], [%1], 16;" :: "r"((uint32_t)(dst)), "l"(src) : "memory")
#define CPCOMMIT() asm volatile("cp.async.commit_group;" ::: "memory")
#define CPWAIT1()  asm volatile("cp.async.wait_group 1;" ::: "memory")
#define CPWAIT0()  asm volatile("cp.async.wait_group 0;" ::: "memory")

__device__ __forceinline__ void ldmx4(uint32_t addr, uint32_t& r0, uint32_t& r1, uint32_t& r2, uint32_t& r3) {
    asm volatile("ldmatrix.sync.aligned.m8n8.x4.shared.b16 {%0,%1,%2,%3}, [%4];"
                 : "=r"(r0), "=r"(r1), "=r"(r2), "=r"(r3) : "r"(addr));
}
__device__ __forceinline__ void mma16816(float* c, const uint32_t* a, uint32_t b0, uint32_t b1) {
    asm volatile("mma.sync.aligned.m16n8k16.row.col.f32.bf16.bf16.f32 "
                 "{%0,%1,%2,%3}, {%4,%5,%6,%7}, {%8,%9}, {%0,%1,%2,%3};"
                 : "+f"(c[0]), "+f"(c[1]), "+f"(c[2]), "+f"(c[3])
                 : "r"(a[0]), "r"(a[1]), "r"(a[2]), "r"(a[3]), "r"(b0), "r"(b1));
}
__device__ __forceinline__ void red_v4(float* p, float a, float b, float c, float d) {
    asm volatile("red.global.add.v4.f32 [%0], {%1,%2,%3,%4};"
                 :: "l"(p), "f"(a), "f"(b), "f"(c), "f"(d) : "memory");
}

// ---------------- geometry setup ----------------
__device__ void inv4d(const double* a_in, double* out) {
    double a[4][8];
    for (int r = 0; r < 4; r++)
        for (int c = 0; c < 4; c++) { a[r][c] = a_in[r*4+c]; a[r][4+c] = (r == c) ? 1.0 : 0.0; }
    for (int col = 0; col < 4; col++) {
        int piv = col; double best = fabs(a[col][col]);
        for (int r = col+1; r < 4; r++) { double t = fabs(a[r][col]); if (t > best) { best = t; piv = r; } }
        if (piv != col) for (int c = 0; c < 8; c++) { double t = a[col][c]; a[col][c] = a[piv][c]; a[piv][c] = t; }
        double dinv = 1.0 / a[col][col];
        for (int c = 0; c < 8; c++) a[col][c] *= dinv;
        for (int r = 0; r < 4; r++) {
            if (r == col) continue;
            double f = a[r][col];
            for (int c = 0; c < 8; c++) a[r][c] -= f * a[col][c];
        }
    }
    for (int r = 0; r < 4; r++) for (int c = 0; c < 4; c++) out[r*4+c] = a[r][4+c];
}
__device__ void mm4(const double* A, const double* B, double* C) {
    for (int r = 0; r < 4; r++) for (int c = 0; c < 4; c++) {
        double s = 0.0;
        for (int k = 0; k < 4; k++) s += A[r*4+k] * B[k*4+c];
        C[r*4+c] = s;
    }
}
__global__ void geo_setup(const float* __restrict__ s2e, const float* __restrict__ s2v,
                          const float* __restrict__ intrin, const float* __restrict__ ida,
                          const float* __restrict__ refh, const float* __restrict__ bda) {
    int i = threadIdx.x;
    if (i >= BN_) return;
    int b = i / 6;
    double M[16], V[16], I[16], E[16], BD[16];
    for (int k = 0; k < 16; k++) {
        M[k] = ida[i*16+k]; V[k] = s2v[i*16+k]; I[k] = intrin[i*16+k];
        E[k] = s2e[i*16+k]; BD[k] = bda[b*16+k];
    }
    double Minv[16], Iinv[16], Vinv[16], CV[16], T[16], CEB[16];
    inv4d(M, Minv); inv4d(I, Iinv); inv4d(V, Vinv);
    mm4(V, Iinv, CV); mm4(E, Vinv, T); mm4(BD, T, CEB);
    float* G = g_geo + i*52;
    for (int k = 0; k < 16; k++) { G[k] = (float)Minv[k]; G[16+k] = (float)CV[k]; G[32+k] = (float)CEB[k]; }
    G[48] = refh[i];
}

// ---------------- zero + packing ----------------
__global__ void zero_all() {
    int gid = blockIdx.x * 256 + threadIdx.x;
    const int tot = (BN_*XROWS*512*2) / 16;
    if (gid >= tot) return;
    uint4 z = {0,0,0,0};
    ((uint4*)g_x1h)[gid] = z; ((uint4*)g_x1l)[gid] = z;
    ((uint4*)g_x2h)[gid] = z; ((uint4*)g_x2l)[gid] = z;
    ((uint4*)g_x3h)[gid] = z; ((uint4*)g_x3l)[gid] = z;
}

// tiled transpose pack: feat [n][ci][704] -> g_x1 [n][prow][512] (hi/lo)
__global__ void pack_feat(const float* __restrict__ feat) {
    __shared__ float sm[32][33];
    int n   = blockIdx.z;
    int ci0 = blockIdx.y * 32;
    int p0  = blockIdx.x * 32;
    int tx = threadIdx.x, ty = threadIdx.y;
#pragma unroll
    for (int i = ty; i < 32; i += 8)
        sm[i][tx] = feat[((size_t)(n*512 + ci0 + i)) * HWp + p0 + tx];
    __syncthreads();
    size_t xbase = (size_t)n * XROWS * 512;
#pragma unroll
    for (int i = ty; i < 32; i += 8) {
        int p = p0 + i;
        int y = p / FWw, x = p % FWw;
        int prow = XOFF + (y + 1) * 46 + (x + 1);
        float v = sm[tx][i];
        __nv_bfloat16 h = __float2bfloat16(v);
        size_t o = xbase + (size_t)prow * 512 + ci0 + tx;
        g_x1h[o] = h;
        g_x1l[o] = __float2bfloat16(v - __bfloat162float(h));
    }
}

// packs BOTH w1 and w2 in one launch
__global__ void pack_w2(const float* __restrict__ wa, const float* __restrict__ wb) {
    int gid = blockIdx.x * 256 + threadIdx.x;
    const int half = 512*9*512;
    if (gid >= 2*half) return;
    int which = (gid >= half);
    int e = which ? (gid - half) : gid;
    int ci = e & 511;
    int t  = (e >> 9) % 9;
    int co = e / (9*512);
    const float* w = which ? wb : wa;
    float v = w[((size_t)co*512 + ci)*9 + t];
    __nv_bfloat16 h = __float2bfloat16(v);
    __nv_bfloat16 l = __float2bfloat16(v - __bfloat162float(h));
    if (which == 0) { g_w1h[e] = h; g_w1l[e] = l; }
    else            { g_w2h[e] = h; g_w2l[e] = l; }
}

__global__ void pack_wo(const float* __restrict__ w) {
    int gid = blockIdx.x * 256 + threadIdx.x;
    if (gid >= 256*512) return;
    int ci = gid & 511;
    int co = gid >> 9;
    float v = (co < CH) ? w[(size_t)co*512 + ci] : 0.f;
    __nv_bfloat16 h = __float2bfloat16(v);
    g_woh[gid] = h;
    g_wol[gid] = __float2bfloat16(v - __bfloat162float(h));
}

// ---------------- HMMA implicit-GEMM conv ----------------
#define ASTRIDE 144
#define T_A  (128*ASTRIDE)
#define OFF_AH 0
#define OFF_AL T_A
#define OFF_BH (2*T_A)
#define OFF_BL (3*T_A)
#define STAGE  (4*T_A)
#define SMEM2  (2*STAGE)

__global__ void __launch_bounds__(256, 1) conv_mma(
    int xsel, int wsel, int taps, int mode, int ysel,
    const float* __restrict__ q0, const float* __restrict__ q1,
    const float* __restrict__ q2, const float* __restrict__ q3)
{
    extern __shared__ __align__(128) uint8_t smd[];
    const uint32_t sb = smem_u32(smd);
    const int tid  = threadIdx.x;
    const int wid  = tid >> 5;
    const int lane = tid & 31;
    const int wm   = wid & 3;
    const int wn   = wid >> 2;
    const int m0   = blockIdx.x * 128;
    const int co0  = blockIdx.y * 128;
    const int n    = blockIdx.z;

    const __nv_bfloat16 *Xhi, *Xlo, *Whi, *Wlo;
    if (xsel == 0)      { Xhi = g_x1h; Xlo = g_x1l; }
    else if (xsel == 1) { Xhi = g_x2h; Xlo = g_x2l; }
    else                { Xhi = g_x3h; Xlo = g_x3l; }
    if (wsel == 0)      { Whi = g_w1h; Wlo = g_w1l; }
    else if (wsel == 1) { Whi = g_w2h; Wlo = g_w2l; }
    else                { Whi = g_woh; Wlo = g_wol; }

    const int steps   = taps * 8;
    const int wstride = taps * 512;
    const size_t xbase = (size_t)n * XROWS * 512;

    float acc[2][8][4];
#pragma unroll
    for (int a = 0; a < 2; a++)
#pragma unroll
        for (int b = 0; b < 8; b++)
#pragma unroll
            for (int c = 0; c < 4; c++) acc[a][b][c] = 0.f;

    auto issue = [&](int s) {
        int t  = s >> 3, ch = s & 7;
        int drow = (taps == 9) ? ((t / 3 - 1) * 46 + (t % 3 - 1)) : 0;
        uint32_t stb = sb + (uint32_t)(s & 1) * STAGE;
        const __nv_bfloat16* xh = Xhi + xbase + (size_t)(XOFF + m0 + drow) * 512 + ch * 64;
        const __nv_bfloat16* xl = Xlo + xbase + (size_t)(XOFF + m0 + drow) * 512 + ch * 64;
        const __nv_bfloat16* wh = Whi + (size_t)co0 * wstride + t * 512 + ch * 64;
        const __nv_bfloat16* wl = Wlo + (size_t)co0 * wstride + t * 512 + ch * 64;
#pragma unroll
        for (int i = 0; i < 4; i++) {
            int idx = i * 256 + tid;
            int r = idx >> 3, cq = idx & 7;
            uint32_t so = (uint32_t)(r * ASTRIDE + cq * 16);
            CP16(stb + OFF_AH + so, xh + (size_t)r * 512     + cq * 8);
            CP16(stb + OFF_AL + so, xl + (size_t)r * 512     + cq * 8);
            CP16(stb + OFF_BH + so, wh + (size_t)r * wstride + cq * 8);
            CP16(stb + OFF_BL + so, wl + (size_t)r * wstride + cq * 8);
        }
        CPCOMMIT();
    };

    issue(0);
    for (int s = 0; s < steps; s++) {
        if (s + 1 < steps) { issue(s + 1); CPWAIT1(); } else { CPWAIT0(); }
        __syncthreads();
        uint32_t stb = sb + (uint32_t)(s & 1) * STAGE;

        const uint32_t a_row  = (uint32_t)(wm * 32 + (lane & 15));
        const uint32_t a_koff = (uint32_t)((lane >> 4) * 16);
        const uint32_t b_nrow = (uint32_t)(wn * 64 + ((lane >> 4) << 3) + (lane & 7));
        const uint32_t b_koff = (uint32_t)(((lane >> 3) & 1) * 16);

#pragma unroll
        for (int ks = 0; ks < 4; ks++) {
            uint32_t kb = (uint32_t)(ks * 32);
            uint32_t ahi[2][4], alo[2][4];
#pragma unroll
            for (int mt = 0; mt < 2; mt++) {
                uint32_t ra = (a_row + mt * 16) * ASTRIDE + kb + a_koff;
                ldmx4(stb + OFF_AH + ra, ahi[mt][0], ahi[mt][1], ahi[mt][2], ahi[mt][3]);
                ldmx4(stb + OFF_AL + ra, alo[mt][0], alo[mt][1], alo[mt][2], alo[mt][3]);
            }
#pragma unroll
            for (int nt2 = 0; nt2 < 4; nt2++) {
                uint32_t rb = (b_nrow + nt2 * 16) * ASTRIDE + kb + b_koff;
                uint32_t bh0, bh1, bh2, bh3, bl0, bl1, bl2, bl3;
                ldmx4(stb + OFF_BH + rb, bh0, bh1, bh2, bh3);
                ldmx4(stb + OFF_BL + rb, bl0, bl1, bl2, bl3);
#pragma unroll
                for (int mt = 0; mt < 2; mt++) {
                    mma16816(acc[mt][nt2*2],   ahi[mt], bh0, bh1);
                    mma16816(acc[mt][nt2*2+1], ahi[mt], bh2, bh3);
                    mma16816(acc[mt][nt2*2],   ahi[mt], bl0, bl1);
                    mma16816(acc[mt][nt2*2+1], ahi[mt], bl2, bl3);
                    mma16816(acc[mt][nt2*2],   alo[mt], bh0, bh1);
                    mma16816(acc[mt][nt2*2+1], alo[mt], bh2, bh3);
                }
            }
        }
        __syncthreads();
    }

    // ---------------- epilogue ----------------
    const int gid = lane >> 2, tig = lane & 3;
    float sc[16], bb[16];
#pragma unroll
    for (int nt = 0; nt < 8; nt++) {
#pragma unroll
        for (int e = 0; e < 2; e++) {
            int co = co0 + wn * 64 + nt * 8 + tig * 2 + e;
            if (mode == 0) {
                float s = q0[co] / sqrtf(q3[co] + 1e-5f);
                sc[nt*2+e] = s;
                bb[nt*2+e] = q1[co] - q2[co] * s;
            } else {
                sc[nt*2+e] = 1.f;
                bb[nt*2+e] = (co < CH) ? q0[co] : 0.f;
            }
        }
    }

    __nv_bfloat16 *Yh = (ysel == 1) ? g_x2h : g_x3h;
    __nv_bfloat16 *Yl = (ysel == 1) ? g_x2l : g_x3l;

#pragma unroll
    for (int mt = 0; mt < 2; mt++) {
#pragma unroll
        for (int rr = 0; rr < 2; rr++) {
            int p = m0 + wm * 32 + mt * 16 + gid + rr * 8;
            int py = p / 46, px = p % 46;
            bool inter = (p < PADP) && (py >= 1) && (py <= 16) && (px >= 1) && (px <= 44);
            if (!inter) continue;
            if (mode == 0) {
                size_t ob = xbase + (size_t)(XOFF + p) * 512 + co0 + wn * 64;
#pragma unroll
                for (int nt = 0; nt < 8; nt++) {
                    float v0 = fmaxf(fmaf(acc[mt][nt][rr*2],   sc[nt*2],   bb[nt*2]),   0.f);
                    float v1 = fmaxf(fmaf(acc[mt][nt][rr*2+1], sc[nt*2+1], bb[nt*2+1]), 0.f);
                    __nv_bfloat16 h0 = __float2bfloat16(v0);
                    __nv_bfloat16 h1 = __float2bfloat16(v1);
                    __nv_bfloat16 l0 = __float2bfloat16(v0 - __bfloat162float(h0));
                    __nv_bfloat16 l1 = __float2bfloat16(v1 - __bfloat162float(h1));
                    size_t o = ob + nt * 8 + tig * 2;
                    *(__nv_bfloat162*)(Yh + o) = __nv_bfloat162(h0, h1);
                    *(__nv_bfloat162*)(Yl + o) = __nv_bfloat162(l0, l1);
                }
            } else {
                int y = py - 1, x = px - 1;
                size_t ob = ((size_t)n * HWp + y * FWw + x) * CH;
#pragma unroll
                for (int nt = 0; nt < 8; nt++) {
#pragma unroll
                    for (int e = 0; e < 2; e++) {
                        int co = co0 + wn * 64 + nt * 8 + tig * 2 + e;
                        if (co < CH)
                            g_hf2[ob + co] = acc[mt][nt][rr*2+e] + bb[nt*2+e];
                    }
                }
            }
        }
    }
}

// ---------------- depth softmax (warp per pixel, channel-last) ----------------
__global__ void softmax2() {
    int r = blockIdx.x * 8 + (threadIdx.x >> 5);
    int lane = threadIdx.x & 31;
    if (r >= RAYS) return;
    float* row = g_hf2 + (size_t)r * CH;
    float v0 = row[lane], v1 = row[lane+32], v2 = row[lane+64];
    float v3 = (lane < 16) ? row[lane+96] : -1e30f;
    float mx = fmaxf(fmaxf(v0, v1), fmaxf(v2, v3));
#pragma unroll
    for (int o = 16; o; o >>= 1) mx = fmaxf(mx, __shfl_xor_sync(0xFFFFFFFF, mx, o));
    float e0 = expf(v0 - mx), e1 = expf(v1 - mx), e2 = expf(v2 - mx);
    float e3 = (lane < 16) ? expf(v3 - mx) : 0.f;
    float sm = e0 + e1 + e2 + e3;
#pragma unroll
    for (int o = 16; o; o >>= 1) sm += __shfl_xor_sync(0xFFFFFFFF, sm, o);
    float inv = 1.f / sm;
    row[lane] = e0 * inv; row[lane+32] = e1 * inv; row[lane+64] = e2 * inv;
    if (lane < 16) row[lane+96] = e3 * inv;
}

// ---------------- per-point voxel index, layout [ray][d] ----------------
__global__ void cells_k() {
    int gid = blockIdx.x * 256 + threadIdx.x;
    if (gid >= NPTS) return;
    int d   = gid % DD;
    int ray = gid / DD;
    int q   = ray % HWp;
    int n   = ray / HWp;
    int wq = q % FWw;
    int hq = q / FWw;

    float X   = wq * (703.0f / 43.0f);
    float Y   = hq * 17.0f;
    float dep = 2.0f + d * (56.0f / 111.0f);

    const float* G = g_geo + n * 52;
    float p0 = G[0]*X  + G[1]*Y  + G[2]*dep  + G[3];
    float p1 = G[4]*X  + G[5]*Y  + G[6]*dep  + G[7];
    float p2 = G[8]*X  + G[9]*Y  + G[10]*dep + G[11];
    float p3 = G[12]*X + G[13]*Y + G[14]*dep + G[15];

    float height = G[48] - p2;
    float c0 = 10.f * p0, c1 = 10.f * p1, c2 = 10.f, c3 = p3;

    const float* CVm = G + 16;
    float q0 = CVm[0]*c0  + CVm[1]*c1  + CVm[2]*c2  + CVm[3]*c3;
    float q1 = CVm[4]*c0  + CVm[5]*c1  + CVm[6]*c2  + CVm[7]*c3;
    float q2 = CVm[8]*c0  + CVm[9]*c1  + CVm[10]*c2 + CVm[11]*c3;

    float ratio = __fdiv_rn(height, q1);
    float r0 = q0 * ratio, r1 = q1 * ratio, r2 = q2 * ratio;

    const float* E = G + 32;
    float g0 = E[0]*r0 + E[1]*r1 + E[2]*r2  + E[3];
    float g1 = E[4]*r0 + E[5]*r1 + E[6]*r2  + E[7];
    float g2 = E[8]*r0 + E[9]*r1 + E[10]*r2 + E[11];

    const float lo = -50.8f - 0.4f;
    float fx = __fdiv_rn(g0 - lo, 0.8f);
    float fy = __fdiv_rn(g1 - lo, 0.8f);
    float fz = __fdiv_rn(g2 + 5.0f, 8.0f);
    int ix = (int)fx;
    int iy = (int)fy;
    int iz = (int)fz;
    bool valid = (ix >= 0) && (iy >= 0) && (iz >= 0) && (ix < 128) && (iy < 128) && (iz < 1);
    g_cells[gid] = valid ? (iy * 128 + ix) : -1;
}

__global__ void zero_bev() {
    int gid = blockIdx.x * 256 + threadIdx.x;
    const int tot = (2*16384*COo) / 4;
    if (gid < tot) ((uint4*)g_bev)[gid] = uint4{0,0,0,0};
}

// ---------------- cooperative ray scatter ----------------
// block = 192 threads per ray: load cells/depth/ctx to smem, compress runs, v4 vector atomics
__global__ void __launch_bounds__(192) scatter3() {
    __shared__ float sdv[DD];
    __shared__ int   scell[DD];
    __shared__ float sctx[COo];
    __shared__ int   srunc[DD];
    __shared__ float sruns[DD];
    __shared__ int   sR;
    const int ray = blockIdx.x;
    const int n   = ray / HWp;
    const int b   = (n >= 6) ? 1 : 0;
    const int tid = threadIdx.x;
    const float* row = g_hf2 + (size_t)ray * CH;

    if (tid < DD) {
        sdv[tid]   = row[tid];
        scell[tid] = g_cells[(size_t)ray * DD + tid];
    } else {
        sctx[tid - DD] = row[tid];     // tid in [112,192) -> ctx[0..79]
    }
    __syncthreads();
    if (tid == 0) {
        int R = 0, prev = -1; float acc = 0.f;
#pragma unroll 4
        for (int d = 0; d < DD; d++) {
            int cl = scell[d];
            if (cl != prev) {
                if (prev >= 0) { srunc[R] = prev; sruns[R] = acc; R++; }
                prev = cl; acc = 0.f;
            }
            acc += sdv[d];
        }
        if (prev >= 0) { srunc[R] = prev; sruns[R] = acc; R++; }
        sR = R;
    }
    __syncthreads();
    const int R = sR;
    if (tid >= 180) return;
    const int g  = tid / 20;            // 0..8
    const int cc = (tid % 20) * 4;      // 0,4,...,76
    const float c0 = sctx[cc], c1 = sctx[cc+1], c2 = sctx[cc+2], c3 = sctx[cc+3];
    float* base = g_bev + (size_t)b * 16384 * COo + cc;
    for (int r = g; r < R; r += 9) {
        float s = sruns[r];
        red_v4(base + (size_t)srunc[r] * COo, s*c0, s*c1, s*c2, s*c3);
    }
}

// ---------------- transpose scratch BEV -> d_out [b][c][cell] ----------------
__global__ void bev_t(float* __restrict__ out) {
    __shared__ float tile[32][COo + 1];
    const int cell0 = blockIdx.x * 32;
    const int b     = blockIdx.y;
    const float* src = g_bev + ((size_t)b * 16384 + cell0) * COo;
    for (int i = threadIdx.x; i < 32 * COo; i += 256) {
        int cl = i / COo, c = i % COo;
        tile[cl][c] = src[i];
    }
    __syncthreads();
    float* dst = out + (size_t)b * COo * 16384 + cell0;
    for (int i = threadIdx.x; i < 32 * COo; i += 256) {
        int c = i / 32, cl = i % 32;
        dst[(size_t)c * 16384 + cl] = tile[cl][c];
    }
}

// ---------------- launch ----------------
extern "C" void kernel_launch(void* const* d_in, const int* in_sizes, int n_in,
                              void* d_out, int out_size) {
    const float* feat   = (const float*)d_in[0];
    const float* w1     = (const float*)d_in[1];
    const float* g1     = (const float*)d_in[2];
    const float* b1     = (const float*)d_in[3];
    const float* m1     = (const float*)d_in[4];
    const float* v1     = (const float*)d_in[5];
    const float* w2     = (const float*)d_in[6];
    const float* g2     = (const float*)d_in[7];
    const float* b2     = (const float*)d_in[8];
    const float* m2     = (const float*)d_in[9];
    const float* v2     = (const float*)d_in[10];
    const float* w_out  = (const float*)d_in[11];
    const float* b_out  = (const float*)d_in[12];
    const float* s2e    = (const float*)d_in[13];
    const float* s2v    = (const float*)d_in[14];
    const float* intrin = (const float*)d_in[15];
    const float* ida    = (const float*)d_in[16];
    const float* refh   = (const float*)d_in[17];
    const float* bda    = (const float*)d_in[18];

    cudaFuncSetAttribute(conv_mma, cudaFuncAttributeMaxDynamicSharedMemorySize, SMEM2);

    geo_setup<<<1, 32>>>(s2e, s2v, intrin, ida, refh, bda);          // 1
    zero_all<<<((BN_*XROWS*512*2/16) + 255) / 256, 256>>>();         // 2
    pack_feat<<<dim3(HWp/32, 16, BN_), dim3(32, 8)>>>(feat);         // 3
    pack_w2<<<(2*512*9*512 + 255) / 256, 256>>>(w1, w2);             // 4

    conv_mma<<<dim3(7, 4, BN_), 256, SMEM2>>>(0, 0, 9, 0, 1, g1, b1, m1, v1);   // 5 (profiled slot)
    conv_mma<<<dim3(7, 4, BN_), 256, SMEM2>>>(1, 1, 9, 0, 2, g2, b2, m2, v2);   // 6

    pack_wo<<<(256*512 + 255) / 256, 256>>>(w_out);                  // 7
    conv_mma<<<dim3(7, 2, BN_), 256, SMEM2>>>(2, 2, 1, 1, 0, b_out, b_out, b_out, b_out); // 8

    softmax2<<<(RAYS + 7) / 8, 256>>>();                             // 9
    cells_k<<<(NPTS + 255) / 256, 256>>>();                          // 10
    zero_bev<<<((2*16384*COo/4) + 255) / 256, 256>>>();              // 11
    scatter3<<<RAYS, 192>>>();                                       // 12
    bev_t<<<dim3(512, 2), 256>>>((float*)d_out);                     // 13
}

// round 6
// speedup vs baseline: 4.7175x; 1.1262x over previous
#include <cuda_runtime.h>
#include <cuda_bf16.h>
#include <math.h>
#include <stdint.h>

#define BN_  12
#define FHh  16
#define FWw  44
#define HWp  704
#define DD   112
#define COo  80
#define CH   192
#define NPTS (BN_*DD*HWp)
#define RAYS (BN_*HWp)

#define XROWS 992          // 48 guard + 828 logical + 116 tail guard
#define XOFF  48
#define PADP  828          // 18*46

// ---------------- persistent device buffers ----------------
__device__ __align__(16) __nv_bfloat16 g_x1h[BN_*XROWS*512];
__device__ __align__(16) __nv_bfloat16 g_x1l[BN_*XROWS*512];
__device__ __align__(16) __nv_bfloat16 g_x2h[BN_*XROWS*512];
__device__ __align__(16) __nv_bfloat16 g_x2l[BN_*XROWS*512];
__device__ __align__(16) __nv_bfloat16 g_x3h[BN_*XROWS*512];
__device__ __align__(16) __nv_bfloat16 g_x3l[BN_*XROWS*512];
__device__ __align__(16) __nv_bfloat16 g_w1h[512*9*512];
__device__ __align__(16) __nv_bfloat16 g_w1l[512*9*512];
__device__ __align__(16) __nv_bfloat16 g_w2h[512*9*512];
__device__ __align__(16) __nv_bfloat16 g_w2l[512*9*512];
__device__ __align__(16) __nv_bfloat16 g_woh[256*512];
__device__ __align__(16) __nv_bfloat16 g_wol[256*512];
__device__ __align__(16) float g_hf2[BN_*HWp*CH];
__device__ __align__(16) float g_bev[2*16384*COo];
__device__ int   g_cells[NPTS];                       // [ray][d]
__device__ float g_geo[BN_*52];

// ---------------- PTX helpers (family-stable only) ----------------
__device__ __forceinline__ uint32_t smem_u32(const void* p) {
    uint32_t a;
    asm("{ .reg .u64 t; cvta.to.shared.u64 t, %1; cvt.u32.u64 %0, t; }" : "=r"(a) : "l"(p));
    return a;
}
#define CP16(dst, src) \
    asm volatile("cp.async.cg.shared.global [%0], [%1], 16;" :: "r"((uint32_t)(dst)), "l"(src) : "memory")
#define CPCOMMIT() asm volatile("cp.async.commit_group;" ::: "memory")
#define CPWAIT1()  asm volatile("cp.async.wait_group 1;" ::: "memory")
#define CPWAIT0()  asm volatile("cp.async.wait_group 0;" ::: "memory")

__device__ __forceinline__ void ldmx4(uint32_t addr, uint32_t& r0, uint32_t& r1, uint32_t& r2, uint32_t& r3) {
    asm volatile("ldmatrix.sync.aligned.m8n8.x4.shared.b16 {%0,%1,%2,%3}, [%4];"
                 : "=r"(r0), "=r"(r1), "=r"(r2), "=r"(r3) : "r"(addr));
}
__device__ __forceinline__ void mma16816(float* c, const uint32_t* a, uint32_t b0, uint32_t b1) {
    asm volatile("mma.sync.aligned.m16n8k16.row.col.f32.bf16.bf16.f32 "
                 "{%0,%1,%2,%3}, {%4,%5,%6,%7}, {%8,%9}, {%0,%1,%2,%3};"
                 : "+f"(c[0]), "+f"(c[1]), "+f"(c[2]), "+f"(c[3])
                 : "r"(a[0]), "r"(a[1]), "r"(a[2]), "r"(a[3]), "r"(b0), "r"(b1));
}
__device__ __forceinline__ void red_v4(float* p, float a, float b, float c, float d) {
    asm volatile("red.global.add.v4.f32 [%0], {%1,%2,%3,%4};"
                 :: "l"(p), "f"(a), "f"(b), "f"(c), "f"(d) : "memory");
}

// ---------------- geometry setup ----------------
__device__ void inv4d(const double* a_in, double* out) {
    double a[4][8];
    for (int r = 0; r < 4; r++)
        for (int c = 0; c < 4; c++) { a[r][c] = a_in[r*4+c]; a[r][4+c] = (r == c) ? 1.0 : 0.0; }
    for (int col = 0; col < 4; col++) {
        int piv = col; double best = fabs(a[col][col]);
        for (int r = col+1; r < 4; r++) { double t = fabs(a[r][col]); if (t > best) { best = t; piv = r; } }
        if (piv != col) for (int c = 0; c < 8; c++) { double t = a[col][c]; a[col][c] = a[piv][c]; a[piv][c] = t; }
        double dinv = 1.0 / a[col][col];
        for (int c = 0; c < 8; c++) a[col][c] *= dinv;
        for (int r = 0; r < 4; r++) {
            if (r == col) continue;
            double f = a[r][col];
            for (int c = 0; c < 8; c++) a[r][c] -= f * a[col][c];
        }
    }
    for (int r = 0; r < 4; r++) for (int c = 0; c < 4; c++) out[r*4+c] = a[r][4+c];
}
__device__ void mm4(const double* A, const double* B, double* C) {
    for (int r = 0; r < 4; r++) for (int c = 0; c < 4; c++) {
        double s = 0.0;
        for (int k = 0; k < 4; k++) s += A[r*4+k] * B[k*4+c];
        C[r*4+c] = s;
    }
}
__global__ void geo_setup(const float* __restrict__ s2e, const float* __restrict__ s2v,
                          const float* __restrict__ intrin, const float* __restrict__ ida,
                          const float* __restrict__ refh, const float* __restrict__ bda) {
    int i = threadIdx.x;
    if (i >= BN_) return;
    int b = i / 6;
    double M[16], V[16], I[16], E[16], BD[16];
    for (int k = 0; k < 16; k++) {
        M[k] = ida[i*16+k]; V[k] = s2v[i*16+k]; I[k] = intrin[i*16+k];
        E[k] = s2e[i*16+k]; BD[k] = bda[b*16+k];
    }
    double Minv[16], Iinv[16], Vinv[16], CV[16], T[16], CEB[16];
    inv4d(M, Minv); inv4d(I, Iinv); inv4d(V, Vinv);
    mm4(V, Iinv, CV); mm4(E, Vinv, T); mm4(BD, T, CEB);
    float* G = g_geo + i*52;
    for (int k = 0; k < 16; k++) { G[k] = (float)Minv[k]; G[16+k] = (float)CV[k]; G[32+k] = (float)CEB[k]; }
    G[48] = refh[i];
}

// ---------------- zero + packing ----------------
__global__ void zero_all() {
    int gid = blockIdx.x * 256 + threadIdx.x;
    const int tot = (BN_*XROWS*512*2) / 16;
    if (gid >= tot) return;
    uint4 z = {0,0,0,0};
    ((uint4*)g_x1h)[gid] = z; ((uint4*)g_x1l)[gid] = z;
    ((uint4*)g_x2h)[gid] = z; ((uint4*)g_x2l)[gid] = z;
    ((uint4*)g_x3h)[gid] = z; ((uint4*)g_x3l)[gid] = z;
}

// tiled transpose pack: feat [n][ci][704] -> g_x1 [n][prow][512] (hi/lo)
__global__ void pack_feat(const float* __restrict__ feat) {
    __shared__ float sm[32][33];
    int n   = blockIdx.z;
    int ci0 = blockIdx.y * 32;
    int p0  = blockIdx.x * 32;
    int tx = threadIdx.x, ty = threadIdx.y;
#pragma unroll
    for (int i = ty; i < 32; i += 8)
        sm[i][tx] = feat[((size_t)(n*512 + ci0 + i)) * HWp + p0 + tx];
    __syncthreads();
    size_t xbase = (size_t)n * XROWS * 512;
#pragma unroll
    for (int i = ty; i < 32; i += 8) {
        int p = p0 + i;
        int y = p / FWw, x = p % FWw;
        int prow = XOFF + (y + 1) * 46 + (x + 1);
        float v = sm[tx][i];
        __nv_bfloat16 h = __float2bfloat16(v);
        size_t o = xbase + (size_t)prow * 512 + ci0 + tx;
        g_x1h[o] = h;
        g_x1l[o] = __float2bfloat16(v - __bfloat162float(h));
    }
}

__global__ void pack_w2(const float* __restrict__ wa, const float* __restrict__ wb) {
    int gid = blockIdx.x * 256 + threadIdx.x;
    const int half = 512*9*512;
    if (gid >= 2*half) return;
    int which = (gid >= half);
    int e = which ? (gid - half) : gid;
    int ci = e & 511;
    int t  = (e >> 9) % 9;
    int co = e / (9*512);
    const float* w = which ? wb : wa;
    float v = w[((size_t)co*512 + ci)*9 + t];
    __nv_bfloat16 h = __float2bfloat16(v);
    __nv_bfloat16 l = __float2bfloat16(v - __bfloat162float(h));
    if (which == 0) { g_w1h[e] = h; g_w1l[e] = l; }
    else            { g_w2h[e] = h; g_w2l[e] = l; }
}

__global__ void pack_wo(const float* __restrict__ w) {
    int gid = blockIdx.x * 256 + threadIdx.x;
    if (gid >= 256*512) return;
    int ci = gid & 511;
    int co = gid >> 9;
    float v = (co < CH) ? w[(size_t)co*512 + ci] : 0.f;
    __nv_bfloat16 h = __float2bfloat16(v);
    g_woh[gid] = h;
    g_wol[gid] = __float2bfloat16(v - __bfloat162float(h));
}

// ---------------- HMMA implicit-GEMM conv (M=64, 2 CTAs/SM) ----------------
// block 256 (8 warps: wm=wid&1 over 2x32 M rows, wn=wid>>1 over 4x32 N cols)
// CTA: M=64 positions x N=128 co, K staged in (tap, 64-ci) chunks, double-buffered.
#define ASTRIDE 144              // bytes per row: 64 bf16 + 16B pad
#define OFF_AH 0
#define OFF_AL (64*ASTRIDE)      // 9216
#define OFF_BH (2*64*ASTRIDE)    // 18432
#define OFF_BL (OFF_BH + 128*ASTRIDE)  // 36864
#define STAGE  (OFF_BL + 128*ASTRIDE)  // 55296
#define SMEM2  (2*STAGE)               // 110592

__global__ void __launch_bounds__(256, 2) conv_mma(
    int xsel, int wsel, int taps, int mode, int ysel,
    const float* __restrict__ q0, const float* __restrict__ q1,
    const float* __restrict__ q2, const float* __restrict__ q3)
{
    extern __shared__ __align__(128) uint8_t smd[];
    const uint32_t sb = smem_u32(smd);
    const int tid  = threadIdx.x;
    const int wid  = tid >> 5;
    const int lane = tid & 31;
    const int wm   = wid & 1;
    const int wn   = wid >> 1;
    const int m0   = blockIdx.x * 64;
    const int co0  = blockIdx.y * 128;
    const int n    = blockIdx.z;

    const __nv_bfloat16 *Xhi, *Xlo, *Whi, *Wlo;
    if (xsel == 0)      { Xhi = g_x1h; Xlo = g_x1l; }
    else if (xsel == 1) { Xhi = g_x2h; Xlo = g_x2l; }
    else                { Xhi = g_x3h; Xlo = g_x3l; }
    if (wsel == 0)      { Whi = g_w1h; Wlo = g_w1l; }
    else if (wsel == 1) { Whi = g_w2h; Wlo = g_w2l; }
    else                { Whi = g_woh; Wlo = g_wol; }

    const int steps   = taps * 8;
    const int wstride = taps * 512;
    const size_t xbase = (size_t)n * XROWS * 512;

    float acc[2][4][4];
#pragma unroll
    for (int a = 0; a < 2; a++)
#pragma unroll
        for (int b = 0; b < 4; b++)
#pragma unroll
            for (int c = 0; c < 4; c++) acc[a][b][c] = 0.f;

    auto issue = [&](int s) {
        int t  = s >> 3, ch = s & 7;
        int drow = (taps == 9) ? ((t / 3 - 1) * 46 + (t % 3 - 1)) : 0;
        uint32_t stb = sb + (uint32_t)(s & 1) * STAGE;
        const __nv_bfloat16* xh = Xhi + xbase + (size_t)(XOFF + m0 + drow) * 512 + ch * 64;
        const __nv_bfloat16* xl = Xlo + xbase + (size_t)(XOFF + m0 + drow) * 512 + ch * 64;
        const __nv_bfloat16* wh = Whi + (size_t)co0 * wstride + t * 512 + ch * 64;
        const __nv_bfloat16* wl = Wlo + (size_t)co0 * wstride + t * 512 + ch * 64;
        // A: 64 rows x 8 chunks = 512 -> 2 per thread per array
#pragma unroll
        for (int i = 0; i < 2; i++) {
            int idx = i * 256 + tid;
            int r = idx >> 3, cq = idx & 7;
            uint32_t so = (uint32_t)(r * ASTRIDE + cq * 16);
            CP16(stb + OFF_AH + so, xh + (size_t)r * 512 + cq * 8);
            CP16(stb + OFF_AL + so, xl + (size_t)r * 512 + cq * 8);
        }
        // B: 128 rows x 8 chunks = 1024 -> 4 per thread per array
#pragma unroll
        for (int i = 0; i < 4; i++) {
            int idx = i * 256 + tid;
            int r = idx >> 3, cq = idx & 7;
            uint32_t so = (uint32_t)(r * ASTRIDE + cq * 16);
            CP16(stb + OFF_BH + so, wh + (size_t)r * wstride + cq * 8);
            CP16(stb + OFF_BL + so, wl + (size_t)r * wstride + cq * 8);
        }
        CPCOMMIT();
    };

    issue(0);
    for (int s = 0; s < steps; s++) {
        if (s + 1 < steps) { issue(s + 1); CPWAIT1(); } else { CPWAIT0(); }
        __syncthreads();
        uint32_t stb = sb + (uint32_t)(s & 1) * STAGE;

        const uint32_t a_row  = (uint32_t)(wm * 32 + (lane & 15));
        const uint32_t a_koff = (uint32_t)((lane >> 4) * 16);
        const uint32_t b_nrow = (uint32_t)(wn * 32 + ((lane >> 4) << 3) + (lane & 7));
        const uint32_t b_koff = (uint32_t)(((lane >> 3) & 1) * 16);

#pragma unroll
        for (int ks = 0; ks < 4; ks++) {
            uint32_t kb = (uint32_t)(ks * 32);
            uint32_t ahi[2][4], alo[2][4];
#pragma unroll
            for (int mt = 0; mt < 2; mt++) {
                uint32_t ra = (a_row + mt * 16) * ASTRIDE + kb + a_koff;
                ldmx4(stb + OFF_AH + ra, ahi[mt][0], ahi[mt][1], ahi[mt][2], ahi[mt][3]);
                ldmx4(stb + OFF_AL + ra, alo[mt][0], alo[mt][1], alo[mt][2], alo[mt][3]);
            }
#pragma unroll
            for (int nt2 = 0; nt2 < 2; nt2++) {
                uint32_t rb = (b_nrow + nt2 * 16) * ASTRIDE + kb + b_koff;
                uint32_t bh0, bh1, bh2, bh3, bl0, bl1, bl2, bl3;
                ldmx4(stb + OFF_BH + rb, bh0, bh1, bh2, bh3);
                ldmx4(stb + OFF_BL + rb, bl0, bl1, bl2, bl3);
#pragma unroll
                for (int mt = 0; mt < 2; mt++) {
                    mma16816(acc[mt][nt2*2],   ahi[mt], bh0, bh1);
                    mma16816(acc[mt][nt2*2+1], ahi[mt], bh2, bh3);
                    mma16816(acc[mt][nt2*2],   ahi[mt], bl0, bl1);
                    mma16816(acc[mt][nt2*2+1], ahi[mt], bl2, bl3);
                    mma16816(acc[mt][nt2*2],   alo[mt], bh0, bh1);
                    mma16816(acc[mt][nt2*2+1], alo[mt], bh2, bh3);
                }
            }
        }
        __syncthreads();
    }

    // ---------------- epilogue ----------------
    const int gid = lane >> 2, tig = lane & 3;
    float sc[8], bb[8];
#pragma unroll
    for (int nt = 0; nt < 4; nt++) {
#pragma unroll
        for (int e = 0; e < 2; e++) {
            int co = co0 + wn * 32 + nt * 8 + tig * 2 + e;
            if (mode == 0) {
                float s = q0[co] / sqrtf(q3[co] + 1e-5f);
                sc[nt*2+e] = s;
                bb[nt*2+e] = q1[co] - q2[co] * s;
            } else {
                sc[nt*2+e] = 1.f;
                bb[nt*2+e] = (co < CH) ? q0[co] : 0.f;
            }
        }
    }

    __nv_bfloat16 *Yh = (ysel == 1) ? g_x2h : g_x3h;
    __nv_bfloat16 *Yl = (ysel == 1) ? g_x2l : g_x3l;

#pragma unroll
    for (int mt = 0; mt < 2; mt++) {
#pragma unroll
        for (int rr = 0; rr < 2; rr++) {
            int p = m0 + wm * 32 + mt * 16 + gid + rr * 8;
            int py = p / 46, px = p % 46;
            bool inter = (p < PADP) && (py >= 1) && (py <= 16) && (px >= 1) && (px <= 44);
            if (!inter) continue;
            if (mode == 0) {
                size_t ob = xbase + (size_t)(XOFF + p) * 512 + co0 + wn * 32;
#pragma unroll
                for (int nt = 0; nt < 4; nt++) {
                    float v0 = fmaxf(fmaf(acc[mt][nt][rr*2],   sc[nt*2],   bb[nt*2]),   0.f);
                    float v1 = fmaxf(fmaf(acc[mt][nt][rr*2+1], sc[nt*2+1], bb[nt*2+1]), 0.f);
                    __nv_bfloat16 h0 = __float2bfloat16(v0);
                    __nv_bfloat16 h1 = __float2bfloat16(v1);
                    __nv_bfloat16 l0 = __float2bfloat16(v0 - __bfloat162float(h0));
                    __nv_bfloat16 l1 = __float2bfloat16(v1 - __bfloat162float(h1));
                    size_t o = ob + nt * 8 + tig * 2;
                    *(__nv_bfloat162*)(Yh + o) = __nv_bfloat162(h0, h1);
                    *(__nv_bfloat162*)(Yl + o) = __nv_bfloat162(l0, l1);
                }
            } else {
                int y = py - 1, x = px - 1;
                size_t ob = ((size_t)n * HWp + y * FWw + x) * CH;
#pragma unroll
                for (int nt = 0; nt < 4; nt++) {
#pragma unroll
                    for (int e = 0; e < 2; e++) {
                        int co = co0 + wn * 32 + nt * 8 + tig * 2 + e;
                        if (co < CH)
                            g_hf2[ob + co] = acc[mt][nt][rr*2+e] + bb[nt*2+e];
                    }
                }
            }
        }
    }
}

// ---------------- depth softmax (warp per pixel, channel-last) ----------------
__global__ void softmax2() {
    int r = blockIdx.x * 8 + (threadIdx.x >> 5);
    int lane = threadIdx.x & 31;
    if (r >= RAYS) return;
    float* row = g_hf2 + (size_t)r * CH;
    float v0 = row[lane], v1 = row[lane+32], v2 = row[lane+64];
    float v3 = (lane < 16) ? row[lane+96] : -1e30f;
    float mx = fmaxf(fmaxf(v0, v1), fmaxf(v2, v3));
#pragma unroll
    for (int o = 16; o; o >>= 1) mx = fmaxf(mx, __shfl_xor_sync(0xFFFFFFFF, mx, o));
    float e0 = expf(v0 - mx), e1 = expf(v1 - mx), e2 = expf(v2 - mx);
    float e3 = (lane < 16) ? expf(v3 - mx) : 0.f;
    float sm = e0 + e1 + e2 + e3;
#pragma unroll
    for (int o = 16; o; o >>= 1) sm += __shfl_xor_sync(0xFFFFFFFF, sm, o);
    float inv = 1.f / sm;
    row[lane] = e0 * inv; row[lane+32] = e1 * inv; row[lane+64] = e2 * inv;
    if (lane < 16) row[lane+96] = e3 * inv;
}

// ---------------- per-point voxel index, layout [ray][d] ----------------
__global__ void cells_k() {
    int gid = blockIdx.x * 256 + threadIdx.x;
    if (gid >= NPTS) return;
    int d   = gid % DD;
    int ray = gid / DD;
    int q   = ray % HWp;
    int n   = ray / HWp;
    int wq = q % FWw;
    int hq = q / FWw;

    float X   = wq * (703.0f / 43.0f);
    float Y   = hq * 17.0f;
    float dep = 2.0f + d * (56.0f / 111.0f);

    const float* G = g_geo + n * 52;
    float p0 = G[0]*X  + G[1]*Y  + G[2]*dep  + G[3];
    float p1 = G[4]*X  + G[5]*Y  + G[6]*dep  + G[7];
    float p2 = G[8]*X  + G[9]*Y  + G[10]*dep + G[11];
    float p3 = G[12]*X + G[13]*Y + G[14]*dep + G[15];

    float height = G[48] - p2;
    float c0 = 10.f * p0, c1 = 10.f * p1, c2 = 10.f, c3 = p3;

    const float* CVm = G + 16;
    float q0 = CVm[0]*c0  + CVm[1]*c1  + CVm[2]*c2  + CVm[3]*c3;
    float q1 = CVm[4]*c0  + CVm[5]*c1  + CVm[6]*c2  + CVm[7]*c3;
    float q2 = CVm[8]*c0  + CVm[9]*c1  + CVm[10]*c2 + CVm[11]*c3;

    float ratio = __fdiv_rn(height, q1);
    float r0 = q0 * ratio, r1 = q1 * ratio, r2 = q2 * ratio;

    const float* E = G + 32;
    float g0 = E[0]*r0 + E[1]*r1 + E[2]*r2  + E[3];
    float g1 = E[4]*r0 + E[5]*r1 + E[6]*r2  + E[7];
    float g2 = E[8]*r0 + E[9]*r1 + E[10]*r2 + E[11];

    const float lo = -50.8f - 0.4f;
    float fx = __fdiv_rn(g0 - lo, 0.8f);
    float fy = __fdiv_rn(g1 - lo, 0.8f);
    float fz = __fdiv_rn(g2 + 5.0f, 8.0f);
    int ix = (int)fx;
    int iy = (int)fy;
    int iz = (int)fz;
    bool valid = (ix >= 0) && (iy >= 0) && (iz >= 0) && (ix < 128) && (iy < 128) && (iz < 1);
    g_cells[gid] = valid ? (iy * 128 + ix) : -1;
}

__global__ void zero_bev() {
    int gid = blockIdx.x * 256 + threadIdx.x;
    const int tot = (2*16384*COo) / 4;
    if (gid < tot) ((uint4*)g_bev)[gid] = uint4{0,0,0,0};
}

// ---------------- cooperative ray scatter ----------------
__global__ void __launch_bounds__(192) scatter3() {
    __shared__ float sdv[DD];
    __shared__ int   scell[DD];
    __shared__ float sctx[COo];
    __shared__ int   srunc[DD];
    __shared__ float sruns[DD];
    __shared__ int   sR;
    const int ray = blockIdx.x;
    const int n   = ray / HWp;
    const int b   = (n >= 6) ? 1 : 0;
    const int tid = threadIdx.x;
    const float* row = g_hf2 + (size_t)ray * CH;

    if (tid < DD) {
        sdv[tid]   = row[tid];
        scell[tid] = g_cells[(size_t)ray * DD + tid];
    } else {
        sctx[tid - DD] = row[tid];
    }
    __syncthreads();
    if (tid == 0) {
        int R = 0, prev = -1; float acc = 0.f;
#pragma unroll 4
        for (int d = 0; d < DD; d++) {
            int cl = scell[d];
            if (cl != prev) {
                if (prev >= 0) { srunc[R] = prev; sruns[R] = acc; R++; }
                prev = cl; acc = 0.f;
            }
            acc += sdv[d];
        }
        if (prev >= 0) { srunc[R] = prev; sruns[R] = acc; R++; }
        sR = R;
    }
    __syncthreads();
    const int R = sR;
    if (tid >= 180) return;
    const int g  = tid / 20;
    const int cc = (tid % 20) * 4;
    const float c0 = sctx[cc], c1 = sctx[cc+1], c2 = sctx[cc+2], c3 = sctx[cc+3];
    float* base = g_bev + (size_t)b * 16384 * COo + cc;
    for (int r = g; r < R; r += 9) {
        float s = sruns[r];
        red_v4(base + (size_t)srunc[r] * COo, s*c0, s*c1, s*c2, s*c3);
    }
}

// ---------------- transpose scratch BEV -> d_out [b][c][cell] ----------------
__global__ void bev_t(float* __restrict__ out) {
    __shared__ float tile[32][COo + 1];
    const int cell0 = blockIdx.x * 32;
    const int b     = blockIdx.y;
    const float* src = g_bev + ((size_t)b * 16384 + cell0) * COo;
    for (int i = threadIdx.x; i < 32 * COo; i += 256) {
        int cl = i / COo, c = i % COo;
        tile[cl][c] = src[i];
    }
    __syncthreads();
    float* dst = out + (size_t)b * COo * 16384 + cell0;
    for (int i = threadIdx.x; i < 32 * COo; i += 256) {
        int c = i / 32, cl = i % 32;
        dst[(size_t)c * 16384 + cl] = tile[cl][c];
    }
}

// ---------------- launch ----------------
extern "C" void kernel_launch(void* const* d_in, const int* in_sizes, int n_in,
                              void* d_out, int out_size) {
    const float* feat   = (const float*)d_in[0];
    const float* w1     = (const float*)d_in[1];
    const float* g1     = (const float*)d_in[2];
    const float* b1     = (const float*)d_in[3];
    const float* m1     = (const float*)d_in[4];
    const float* v1     = (const float*)d_in[5];
    const float* w2     = (const float*)d_in[6];
    const float* g2     = (const float*)d_in[7];
    const float* b2     = (const float*)d_in[8];
    const float* m2     = (const float*)d_in[9];
    const float* v2     = (const float*)d_in[10];
    const float* w_out  = (const float*)d_in[11];
    const float* b_out  = (const float*)d_in[12];
    const float* s2e    = (const float*)d_in[13];
    const float* s2v    = (const float*)d_in[14];
    const float* intrin = (const float*)d_in[15];
    const float* ida    = (const float*)d_in[16];
    const float* refh   = (const float*)d_in[17];
    const float* bda    = (const float*)d_in[18];

    cudaFuncSetAttribute(conv_mma, cudaFuncAttributeMaxDynamicSharedMemorySize, SMEM2);

    zero_all<<<((BN_*XROWS*512*2/16) + 255) / 256, 256>>>();         // 1
    pack_feat<<<dim3(HWp/32, 16, BN_), dim3(32, 8)>>>(feat);         // 2
    pack_w2<<<(2*512*9*512 + 255) / 256, 256>>>(w1, w2);             // 3

    conv_mma<<<dim3(13, 4, BN_), 256, SMEM2>>>(0, 0, 9, 0, 1, g1, b1, m1, v1);   // 4 <- profiled slot
    conv_mma<<<dim3(13, 4, BN_), 256, SMEM2>>>(1, 1, 9, 0, 2, g2, b2, m2, v2);   // 5

    pack_wo<<<(256*512 + 255) / 256, 256>>>(w_out);                  // 6
    conv_mma<<<dim3(13, 2, BN_), 256, SMEM2>>>(2, 2, 1, 1, 0, b_out, b_out, b_out, b_out); // 7

    geo_setup<<<1, 32>>>(s2e, s2v, intrin, ida, refh, bda);          // 8
    softmax2<<<(RAYS + 7) / 8, 256>>>();                             // 9
    cells_k<<<(NPTS + 255) / 256, 256>>>();                          // 10
    zero_bev<<<((2*16384*COo/4) + 255) / 256, 256>>>();              // 11
    scatter3<<<RAYS, 192>>>();                                       // 12
    bev_t<<<dim3(512, 2), 256>>>((float*)d_out);                     // 13
}

// round 7
// speedup vs baseline: 5.1948x; 1.1012x over previous
#include <cuda_runtime.h>
#include <cuda_bf16.h>
#include <math.h>
#include <stdint.h>

#define BN_  12
#define FHh  16
#define FWw  44
#define HWp  704
#define DD   112
#define COo  80
#define CH   192
#define NPTS (BN_*DD*HWp)
#define RAYS (BN_*HWp)

#define XROWS 992          // 48 guard + 828 logical + 116 tail guard
#define XOFF  48
#define PADP  828          // 18*46

// ---------------- persistent device buffers ----------------
__device__ __align__(16) __nv_bfloat16 g_x1h[BN_*XROWS*512];
__device__ __align__(16) __nv_bfloat16 g_x1l[BN_*XROWS*512];
__device__ __align__(16) __nv_bfloat16 g_x2h[BN_*XROWS*512];
__device__ __align__(16) __nv_bfloat16 g_x2l[BN_*XROWS*512];
__device__ __align__(16) __nv_bfloat16 g_x3h[BN_*XROWS*512];
__device__ __align__(16) __nv_bfloat16 g_x3l[BN_*XROWS*512];
__device__ __align__(16) __nv_bfloat16 g_w1h[512*9*512];
__device__ __align__(16) __nv_bfloat16 g_w1l[512*9*512];
__device__ __align__(16) __nv_bfloat16 g_w2h[512*9*512];
__device__ __align__(16) __nv_bfloat16 g_w2l[512*9*512];
__device__ __align__(16) __nv_bfloat16 g_woh[256*512];
__device__ __align__(16) __nv_bfloat16 g_wol[256*512];
__device__ __align__(16) float g_hf2[BN_*HWp*CH];
__device__ __align__(16) float g_bev[2*16384*COo];
__device__ int   g_cells[NPTS];                       // [ray][d]
__device__ float g_geo[BN_*52];

// ---------------- PTX helpers (family-stable only) ----------------
__device__ __forceinline__ uint32_t smem_u32(const void* p) {
    uint32_t a;
    asm("{ .reg .u64 t; cvta.to.shared.u64 t, %1; cvt.u32.u64 %0, t; }" : "=r"(a) : "l"(p));
    return a;
}
#define CP16(dst, src) \
    asm volatile("cp.async.cg.shared.global [%0], [%1], 16;" :: "r"((uint32_t)(dst)), "l"(src) : "memory")
#define CPCOMMIT() asm volatile("cp.async.commit_group;" ::: "memory")
#define CPWAITN(n) asm volatile("cp.async.wait_group %0;" :: "n"(n) : "memory")

__device__ __forceinline__ void ldmx4(uint32_t addr, uint32_t& r0, uint32_t& r1, uint32_t& r2, uint32_t& r3) {
    asm volatile("ldmatrix.sync.aligned.m8n8.x4.shared.b16 {%0,%1,%2,%3}, [%4];"
                 : "=r"(r0), "=r"(r1), "=r"(r2), "=r"(r3) : "r"(addr));
}
__device__ __forceinline__ void mma16816(float* c, const uint32_t* a, uint32_t b0, uint32_t b1) {
    asm volatile("mma.sync.aligned.m16n8k16.row.col.f32.bf16.bf16.f32 "
                 "{%0,%1,%2,%3}, {%4,%5,%6,%7}, {%8,%9}, {%0,%1,%2,%3};"
                 : "+f"(c[0]), "+f"(c[1]), "+f"(c[2]), "+f"(c[3])
                 : "r"(a[0]), "r"(a[1]), "r"(a[2]), "r"(a[3]), "r"(b0), "r"(b1));
}
__device__ __forceinline__ void red_v4(float* p, float a, float b, float c, float d) {
    asm volatile("red.global.add.v4.f32 [%0], {%1,%2,%3,%4};"
                 :: "l"(p), "f"(a), "f"(b), "f"(c), "f"(d) : "memory");
}

// ---------------- geometry setup ----------------
__device__ void inv4d(const double* a_in, double* out) {
    double a[4][8];
    for (int r = 0; r < 4; r++)
        for (int c = 0; c < 4; c++) { a[r][c] = a_in[r*4+c]; a[r][4+c] = (r == c) ? 1.0 : 0.0; }
    for (int col = 0; col < 4; col++) {
        int piv = col; double best = fabs(a[col][col]);
        for (int r = col+1; r < 4; r++) { double t = fabs(a[r][col]); if (t > best) { best = t; piv = r; } }
        if (piv != col) for (int c = 0; c < 8; c++) { double t = a[col][c]; a[col][c] = a[piv][c]; a[piv][c] = t; }
        double dinv = 1.0 / a[col][col];
        for (int c = 0; c < 8; c++) a[col][c] *= dinv;
        for (int r = 0; r < 4; r++) {
            if (r == col) continue;
            double f = a[r][col];
            for (int c = 0; c < 8; c++) a[r][c] -= f * a[col][c];
        }
    }
    for (int r = 0; r < 4; r++) for (int c = 0; c < 4; c++) out[r*4+c] = a[r][4+c];
}
__device__ void mm4(const double* A, const double* B, double* C) {
    for (int r = 0; r < 4; r++) for (int c = 0; c < 4; c++) {
        double s = 0.0;
        for (int k = 0; k < 4; k++) s += A[r*4+k] * B[k*4+c];
        C[r*4+c] = s;
    }
}
__global__ void geo_setup(const float* __restrict__ s2e, const float* __restrict__ s2v,
                          const float* __restrict__ intrin, const float* __restrict__ ida,
                          const float* __restrict__ refh, const float* __restrict__ bda) {
    int i = threadIdx.x;
    if (i >= BN_) return;
    int b = i / 6;
    double M[16], V[16], I[16], E[16], BD[16];
    for (int k = 0; k < 16; k++) {
        M[k] = ida[i*16+k]; V[k] = s2v[i*16+k]; I[k] = intrin[i*16+k];
        E[k] = s2e[i*16+k]; BD[k] = bda[b*16+k];
    }
    double Minv[16], Iinv[16], Vinv[16], CV[16], T[16], CEB[16];
    inv4d(M, Minv); inv4d(I, Iinv); inv4d(V, Vinv);
    mm4(V, Iinv, CV); mm4(E, Vinv, T); mm4(BD, T, CEB);
    float* G = g_geo + i*52;
    for (int k = 0; k < 16; k++) { G[k] = (float)Minv[k]; G[16+k] = (float)CV[k]; G[32+k] = (float)CEB[k]; }
    G[48] = refh[i];
}

// ---------------- zero + packing ----------------
__global__ void zero_all() {
    int gid = blockIdx.x * 256 + threadIdx.x;
    const int tot = (BN_*XROWS*512*2) / 16;
    if (gid >= tot) return;
    uint4 z = {0,0,0,0};
    ((uint4*)g_x1h)[gid] = z; ((uint4*)g_x1l)[gid] = z;
    ((uint4*)g_x2h)[gid] = z; ((uint4*)g_x2l)[gid] = z;
    ((uint4*)g_x3h)[gid] = z; ((uint4*)g_x3l)[gid] = z;
}

// tiled transpose pack: feat [n][ci][704] -> g_x1 [n][prow][512] (hi/lo)
__global__ void pack_feat(const float* __restrict__ feat) {
    __shared__ float sm[32][33];
    int n   = blockIdx.z;
    int ci0 = blockIdx.y * 32;
    int p0  = blockIdx.x * 32;
    int tx = threadIdx.x, ty = threadIdx.y;
#pragma unroll
    for (int i = ty; i < 32; i += 8)
        sm[i][tx] = feat[((size_t)(n*512 + ci0 + i)) * HWp + p0 + tx];
    __syncthreads();
    size_t xbase = (size_t)n * XROWS * 512;
#pragma unroll
    for (int i = ty; i < 32; i += 8) {
        int p = p0 + i;
        int y = p / FWw, x = p % FWw;
        int prow = XOFF + (y + 1) * 46 + (x + 1);
        float v = sm[tx][i];
        __nv_bfloat16 h = __float2bfloat16(v);
        size_t o = xbase + (size_t)prow * 512 + ci0 + tx;
        g_x1h[o] = h;
        g_x1l[o] = __float2bfloat16(v - __bfloat162float(h));
    }
}

__global__ void pack_w2(const float* __restrict__ wa, const float* __restrict__ wb) {
    int gid = blockIdx.x * 256 + threadIdx.x;
    const int half = 512*9*512;
    if (gid >= 2*half) return;
    int which = (gid >= half);
    int e = which ? (gid - half) : gid;
    int ci = e & 511;
    int t  = (e >> 9) % 9;
    int co = e / (9*512);
    const float* w = which ? wb : wa;
    float v = w[((size_t)co*512 + ci)*9 + t];
    __nv_bfloat16 h = __float2bfloat16(v);
    __nv_bfloat16 l = __float2bfloat16(v - __bfloat162float(h));
    if (which == 0) { g_w1h[e] = h; g_w1l[e] = l; }
    else            { g_w2h[e] = h; g_w2l[e] = l; }
}

__global__ void pack_wo(const float* __restrict__ w) {
    int gid = blockIdx.x * 256 + threadIdx.x;
    if (gid >= 256*512) return;
    int ci = gid & 511;
    int co = gid >> 9;
    float v = (co < CH) ? w[(size_t)co*512 + ci] : 0.f;
    __nv_bfloat16 h = __float2bfloat16(v);
    g_woh[gid] = h;
    g_wol[gid] = __float2bfloat16(v - __bfloat162float(h));
}

// ---------------- HMMA implicit-GEMM conv (M=64, N=128, 32-ci stages, 4-deep) ----------------
// block 256 (8 warps: wm=wid&1 over 2x32 M rows, wn=wid>>1 over 4x32 N cols)
// Stage = (tap, 32-ci chunk). SMEM rows are 64B with XOR-16B-chunk swizzle c ^ ((r>>1)&3).
#define OFF_AH 0
#define OFF_AL 4096
#define OFF_BH 8192
#define OFF_BL 16384
#define STAGE  24576
#define PDEPTH 4
#define SMEM2  (PDEPTH*STAGE)    // 98304

__global__ void __launch_bounds__(256, 2) conv_mma(
    int xsel, int wsel, int taps, int mode, int ysel,
    const float* __restrict__ q0, const float* __restrict__ q1,
    const float* __restrict__ q2, const float* __restrict__ q3)
{
    extern __shared__ __align__(128) uint8_t smd[];
    const uint32_t sb = smem_u32(smd);
    const int tid  = threadIdx.x;
    const int wid  = tid >> 5;
    const int lane = tid & 31;
    const int wm   = wid & 1;
    const int wn   = wid >> 1;
    const int m0   = blockIdx.x * 64;
    const int co0  = blockIdx.y * 128;
    const int n    = blockIdx.z;

    const __nv_bfloat16 *Xhi, *Xlo, *Whi, *Wlo;
    if (xsel == 0)      { Xhi = g_x1h; Xlo = g_x1l; }
    else if (xsel == 1) { Xhi = g_x2h; Xlo = g_x2l; }
    else                { Xhi = g_x3h; Xlo = g_x3l; }
    if (wsel == 0)      { Whi = g_w1h; Wlo = g_w1l; }
    else if (wsel == 1) { Whi = g_w2h; Wlo = g_w2l; }
    else                { Whi = g_woh; Wlo = g_wol; }

    const int steps   = taps * 16;          // 32-ci chunks
    const int wstride = taps * 512;
    const size_t xbase = (size_t)n * XROWS * 512;

    float acc[2][4][4];
#pragma unroll
    for (int a = 0; a < 2; a++)
#pragma unroll
        for (int b = 0; b < 4; b++)
#pragma unroll
            for (int c = 0; c < 4; c++) acc[a][b][c] = 0.f;

    // cp.async assignments (swizzled 16B chunks)
    const int ar  = tid >> 2;            // 0..63
    const int acq = tid & 3;
    const uint32_t aso = (uint32_t)(ar * 64 + ((acq ^ ((ar >> 1) & 3)) * 16));

    auto issue = [&](int s) {
        int t  = s >> 4, ch = s & 15;
        int drow = (taps == 9) ? ((t / 3 - 1) * 46 + (t % 3 - 1)) : 0;
        uint32_t stb = sb + (uint32_t)(s & (PDEPTH-1)) * STAGE;
        const __nv_bfloat16* xh = Xhi + xbase + (size_t)(XOFF + m0 + drow) * 512 + ch * 32;
        const __nv_bfloat16* xl = Xlo + xbase + (size_t)(XOFF + m0 + drow) * 512 + ch * 32;
        const __nv_bfloat16* wh = Whi + (size_t)co0 * wstride + t * 512 + ch * 32;
        const __nv_bfloat16* wl = Wlo + (size_t)co0 * wstride + t * 512 + ch * 32;
        // A: 64 rows x 4 chunks = 256 -> 1 per thread per array
        CP16(stb + OFF_AH + aso, xh + (size_t)ar * 512 + acq * 8);
        CP16(stb + OFF_AL + aso, xl + (size_t)ar * 512 + acq * 8);
        // B: 128 rows x 4 chunks = 512 -> 2 per thread per array
#pragma unroll
        for (int i = 0; i < 2; i++) {
            int idx = i * 256 + tid;
            int r = idx >> 2, cq = idx & 3;
            uint32_t so = (uint32_t)(r * 64 + ((cq ^ ((r >> 1) & 3)) * 16));
            CP16(stb + OFF_BH + so, wh + (size_t)r * wstride + cq * 8);
            CP16(stb + OFF_BL + so, wl + (size_t)r * wstride + cq * 8);
        }
        CPCOMMIT();
    };

    issue(0); issue(1); issue(2);

    // ldmatrix address components (swizzle value invariant under +16 rows)
    const uint32_t a_row = (uint32_t)(wm * 32 + (lane & 15));
    const uint32_t a_hi  = (uint32_t)(lane >> 4);            // k-chunk bit0
    const uint32_t sA    = (a_row >> 1) & 3;
    const uint32_t b_row = (uint32_t)(wn * 32 + ((lane >> 4) << 3) + (lane & 7));
    const uint32_t b_hi  = (uint32_t)((lane >> 3) & 1);
    const uint32_t sB    = (b_row >> 1) & 3;

    for (int s = 0; s < steps; s++) {
        int rem = steps - 1 - s;
        if (rem >= 2)      CPWAITN(2);
        else if (rem == 1) CPWAITN(1);
        else               CPWAITN(0);
        __syncthreads();
        if (s + 3 < steps) issue(s + 3);

        uint32_t stb = sb + (uint32_t)(s & (PDEPTH-1)) * STAGE;

#pragma unroll
        for (int ks = 0; ks < 2; ks++) {
            uint32_t ca = (uint32_t)(((ks << 1) + a_hi) ^ sA) * 16;
            uint32_t cb = (uint32_t)(((ks << 1) + b_hi) ^ sB) * 16;
            uint32_t ahi[2][4], alo[2][4];
#pragma unroll
            for (int mt = 0; mt < 2; mt++) {
                uint32_t ra = stb + (a_row + mt * 16) * 64 + ca;
                ldmx4(ra + OFF_AH, ahi[mt][0], ahi[mt][1], ahi[mt][2], ahi[mt][3]);
                ldmx4(ra + OFF_AL, alo[mt][0], alo[mt][1], alo[mt][2], alo[mt][3]);
            }
#pragma unroll
            for (int nt2 = 0; nt2 < 2; nt2++) {
                uint32_t rb = stb + (b_row + nt2 * 16) * 64 + cb;
                uint32_t bh0, bh1, bh2, bh3, bl0, bl1, bl2, bl3;
                ldmx4(rb + OFF_BH, bh0, bh1, bh2, bh3);
                ldmx4(rb + OFF_BL, bl0, bl1, bl2, bl3);
#pragma unroll
                for (int mt = 0; mt < 2; mt++) {
                    mma16816(acc[mt][nt2*2],   ahi[mt], bh0, bh1);
                    mma16816(acc[mt][nt2*2+1], ahi[mt], bh2, bh3);
                    mma16816(acc[mt][nt2*2],   ahi[mt], bl0, bl1);
                    mma16816(acc[mt][nt2*2+1], ahi[mt], bl2, bl3);
                    mma16816(acc[mt][nt2*2],   alo[mt], bh0, bh1);
                    mma16816(acc[mt][nt2*2+1], alo[mt], bh2, bh3);
                }
            }
        }
    }

    // ---------------- epilogue ----------------
    const int gid = lane >> 2, tig = lane & 3;
    float sc[8], bb[8];
#pragma unroll
    for (int nt = 0; nt < 4; nt++) {
#pragma unroll
        for (int e = 0; e < 2; e++) {
            int co = co0 + wn * 32 + nt * 8 + tig * 2 + e;
            if (mode == 0) {
                float s = q0[co] / sqrtf(q3[co] + 1e-5f);
                sc[nt*2+e] = s;
                bb[nt*2+e] = q1[co] - q2[co] * s;
            } else {
                sc[nt*2+e] = 1.f;
                bb[nt*2+e] = (co < CH) ? q0[co] : 0.f;
            }
        }
    }

    __nv_bfloat16 *Yh = (ysel == 1) ? g_x2h : g_x3h;
    __nv_bfloat16 *Yl = (ysel == 1) ? g_x2l : g_x3l;

#pragma unroll
    for (int mt = 0; mt < 2; mt++) {
#pragma unroll
        for (int rr = 0; rr < 2; rr++) {
            int p = m0 + wm * 32 + mt * 16 + gid + rr * 8;
            int py = p / 46, px = p % 46;
            bool inter = (p < PADP) && (py >= 1) && (py <= 16) && (px >= 1) && (px <= 44);
            if (!inter) continue;
            if (mode == 0) {
                size_t ob = xbase + (size_t)(XOFF + p) * 512 + co0 + wn * 32;
#pragma unroll
                for (int nt = 0; nt < 4; nt++) {
                    float v0 = fmaxf(fmaf(acc[mt][nt][rr*2],   sc[nt*2],   bb[nt*2]),   0.f);
                    float v1 = fmaxf(fmaf(acc[mt][nt][rr*2+1], sc[nt*2+1], bb[nt*2+1]), 0.f);
                    __nv_bfloat16 h0 = __float2bfloat16(v0);
                    __nv_bfloat16 h1 = __float2bfloat16(v1);
                    __nv_bfloat16 l0 = __float2bfloat16(v0 - __bfloat162float(h0));
                    __nv_bfloat16 l1 = __float2bfloat16(v1 - __bfloat162float(h1));
                    size_t o = ob + nt * 8 + tig * 2;
                    *(__nv_bfloat162*)(Yh + o) = __nv_bfloat162(h0, h1);
                    *(__nv_bfloat162*)(Yl + o) = __nv_bfloat162(l0, l1);
                }
            } else {
                int y = py - 1, x = px - 1;
                size_t ob = ((size_t)n * HWp + y * FWw + x) * CH;
#pragma unroll
                for (int nt = 0; nt < 4; nt++) {
#pragma unroll
                    for (int e = 0; e < 2; e++) {
                        int co = co0 + wn * 32 + nt * 8 + tig * 2 + e;
                        if (co < CH)
                            g_hf2[ob + co] = acc[mt][nt][rr*2+e] + bb[nt*2+e];
                    }
                }
            }
        }
    }
}

// ---------------- depth softmax (warp per pixel, channel-last) ----------------
__global__ void softmax2() {
    int r = blockIdx.x * 8 + (threadIdx.x >> 5);
    int lane = threadIdx.x & 31;
    if (r >= RAYS) return;
    float* row = g_hf2 + (size_t)r * CH;
    float v0 = row[lane], v1 = row[lane+32], v2 = row[lane+64];
    float v3 = (lane < 16) ? row[lane+96] : -1e30f;
    float mx = fmaxf(fmaxf(v0, v1), fmaxf(v2, v3));
#pragma unroll
    for (int o = 16; o; o >>= 1) mx = fmaxf(mx, __shfl_xor_sync(0xFFFFFFFF, mx, o));
    float e0 = expf(v0 - mx), e1 = expf(v1 - mx), e2 = expf(v2 - mx);
    float e3 = (lane < 16) ? expf(v3 - mx) : 0.f;
    float sm = e0 + e1 + e2 + e3;
#pragma unroll
    for (int o = 16; o; o >>= 1) sm += __shfl_xor_sync(0xFFFFFFFF, sm, o);
    float inv = 1.f / sm;
    row[lane] = e0 * inv; row[lane+32] = e1 * inv; row[lane+64] = e2 * inv;
    if (lane < 16) row[lane+96] = e3 * inv;
}

// ---------------- per-point voxel index, layout [ray][d] ----------------
__global__ void cells_k() {
    int gid = blockIdx.x * 256 + threadIdx.x;
    if (gid >= NPTS) return;
    int d   = gid % DD;
    int ray = gid / DD;
    int q   = ray % HWp;
    int n   = ray / HWp;
    int wq = q % FWw;
    int hq = q / FWw;

    float X   = wq * (703.0f / 43.0f);
    float Y   = hq * 17.0f;
    float dep = 2.0f + d * (56.0f / 111.0f);

    const float* G = g_geo + n * 52;
    float p0 = G[0]*X  + G[1]*Y  + G[2]*dep  + G[3];
    float p1 = G[4]*X  + G[5]*Y  + G[6]*dep  + G[7];
    float p2 = G[8]*X  + G[9]*Y  + G[10]*dep + G[11];
    float p3 = G[12]*X + G[13]*Y + G[14]*dep + G[15];

    float height = G[48] - p2;
    float c0 = 10.f * p0, c1 = 10.f * p1, c2 = 10.f, c3 = p3;

    const float* CVm = G + 16;
    float q0 = CVm[0]*c0  + CVm[1]*c1  + CVm[2]*c2  + CVm[3]*c3;
    float q1 = CVm[4]*c0  + CVm[5]*c1  + CVm[6]*c2  + CVm[7]*c3;
    float q2 = CVm[8]*c0  + CVm[9]*c1  + CVm[10]*c2 + CVm[11]*c3;

    float ratio = __fdiv_rn(height, q1);
    float r0 = q0 * ratio, r1 = q1 * ratio, r2 = q2 * ratio;

    const float* E = G + 32;
    float g0 = E[0]*r0 + E[1]*r1 + E[2]*r2  + E[3];
    float g1 = E[4]*r0 + E[5]*r1 + E[6]*r2  + E[7];
    float g2 = E[8]*r0 + E[9]*r1 + E[10]*r2 + E[11];

    const float lo = -50.8f - 0.4f;
    float fx = __fdiv_rn(g0 - lo, 0.8f);
    float fy = __fdiv_rn(g1 - lo, 0.8f);
    float fz = __fdiv_rn(g2 + 5.0f, 8.0f);
    int ix = (int)fx;
    int iy = (int)fy;
    int iz = (int)fz;
    bool valid = (ix >= 0) && (iy >= 0) && (iz >= 0) && (ix < 128) && (iy < 128) && (iz < 1);
    g_cells[gid] = valid ? (iy * 128 + ix) : -1;
}

__global__ void zero_bev() {
    int gid = blockIdx.x * 256 + threadIdx.x;
    const int tot = (2*16384*COo) / 4;
    if (gid < tot) ((uint4*)g_bev)[gid] = uint4{0,0,0,0};
}

// ---------------- cooperative ray scatter ----------------
__global__ void __launch_bounds__(192) scatter3() {
    __shared__ float sdv[DD];
    __shared__ int   scell[DD];
    __shared__ float sctx[COo];
    __shared__ int   srunc[DD];
    __shared__ float sruns[DD];
    __shared__ int   sR;
    const int ray = blockIdx.x;
    const int n   = ray / HWp;
    const int b   = (n >= 6) ? 1 : 0;
    const int tid = threadIdx.x;
    const float* row = g_hf2 + (size_t)ray * CH;

    if (tid < DD) {
        sdv[tid]   = row[tid];
        scell[tid] = g_cells[(size_t)ray * DD + tid];
    } else {
        sctx[tid - DD] = row[tid];
    }
    __syncthreads();
    if (tid == 0) {
        int R = 0, prev = -1; float acc = 0.f;
#pragma unroll 4
        for (int d = 0; d < DD; d++) {
            int cl = scell[d];
            if (cl != prev) {
                if (prev >= 0) { srunc[R] = prev; sruns[R] = acc; R++; }
                prev = cl; acc = 0.f;
            }
            acc += sdv[d];
        }
        if (prev >= 0) { srunc[R] = prev; sruns[R] = acc; R++; }
        sR = R;
    }
    __syncthreads();
    const int R = sR;
    if (tid >= 180) return;
    const int g  = tid / 20;
    const int cc = (tid % 20) * 4;
    const float c0 = sctx[cc], c1 = sctx[cc+1], c2 = sctx[cc+2], c3 = sctx[cc+3];
    float* base = g_bev + (size_t)b * 16384 * COo + cc;
    for (int r = g; r < R; r += 9) {
        float s = sruns[r];
        red_v4(base + (size_t)srunc[r] * COo, s*c0, s*c1, s*c2, s*c3);
    }
}

// ---------------- transpose scratch BEV -> d_out [b][c][cell] ----------------
__global__ void bev_t(float* __restrict__ out) {
    __shared__ float tile[32][COo + 1];
    const int cell0 = blockIdx.x * 32;
    const int b     = blockIdx.y;
    const float* src = g_bev + ((size_t)b * 16384 + cell0) * COo;
    for (int i = threadIdx.x; i < 32 * COo; i += 256) {
        int cl = i / COo, c = i % COo;
        tile[cl][c] = src[i];
    }
    __syncthreads();
    float* dst = out + (size_t)b * COo * 16384 + cell0;
    for (int i = threadIdx.x; i < 32 * COo; i += 256) {
        int c = i / 32, cl = i % 32;
        dst[(size_t)c * 16384 + cl] = tile[cl][c];
    }
}

// ---------------- launch ----------------
extern "C" void kernel_launch(void* const* d_in, const int* in_sizes, int n_in,
                              void* d_out, int out_size) {
    const float* feat   = (const float*)d_in[0];
    const float* w1     = (const float*)d_in[1];
    const float* g1     = (const float*)d_in[2];
    const float* b1     = (const float*)d_in[3];
    const float* m1     = (const float*)d_in[4];
    const float* v1     = (const float*)d_in[5];
    const float* w2     = (const float*)d_in[6];
    const float* g2     = (const float*)d_in[7];
    const float* b2     = (const float*)d_in[8];
    const float* m2     = (const float*)d_in[9];
    const float* v2     = (const float*)d_in[10];
    const float* w_out  = (const float*)d_in[11];
    const float* b_out  = (const float*)d_in[12];
    const float* s2e    = (const float*)d_in[13];
    const float* s2v    = (const float*)d_in[14];
    const float* intrin = (const float*)d_in[15];
    const float* ida    = (const float*)d_in[16];
    const float* refh   = (const float*)d_in[17];
    const float* bda    = (const float*)d_in[18];

    cudaFuncSetAttribute(conv_mma, cudaFuncAttributeMaxDynamicSharedMemorySize, SMEM2);

    zero_all<<<((BN_*XROWS*512*2/16) + 255) / 256, 256>>>();         // 1
    pack_feat<<<dim3(HWp/32, 16, BN_), dim3(32, 8)>>>(feat);         // 2
    pack_w2<<<(2*512*9*512 + 255) / 256, 256>>>(w1, w2);             // 3

    conv_mma<<<dim3(13, 4, BN_), 256, SMEM2>>>(0, 0, 9, 0, 1, g1, b1, m1, v1);   // 4 <- profiled slot
    conv_mma<<<dim3(13, 4, BN_), 256, SMEM2>>>(1, 1, 9, 0, 2, g2, b2, m2, v2);   // 5

    pack_wo<<<(256*512 + 255) / 256, 256>>>(w_out);                  // 6
    conv_mma<<<dim3(13, 2, BN_), 256, SMEM2>>>(2, 2, 1, 1, 0, b_out, b_out, b_out, b_out); // 7

    geo_setup<<<1, 32>>>(s2e, s2v, intrin, ida, refh, bda);          // 8
    softmax2<<<(RAYS + 7) / 8, 256>>>();                             // 9
    cells_k<<<(NPTS + 255) / 256, 256>>>();                          // 10
    zero_bev<<<((2*16384*COo/4) + 255) / 256, 256>>>();              // 11
    scatter3<<<RAYS, 192>>>();                                       // 12
    bev_t<<<dim3(512, 2), 256>>>((float*)d_out);                     // 13
}